// round 1
// baseline (speedup 1.0000x reference)
#include <cuda_runtime.h>
#include <math.h>

#define BB 16
#define CC 512
#define LL 1024
#define GG 32
#define CPG 16
#define HEADS 8
#define CHH 64

// Scratch (no allocation allowed): h (32MB), qkv (96MB)
__device__ float g_h[BB * CC * LL];
__device__ float g_qkv[BB * 3 * CC * LL];

// ---------------------------------------------------------------------------
// Kernel 1: GroupNorm(32).  One block per (b, g). Reduce 16*1024 elements.
// ---------------------------------------------------------------------------
__global__ void gn_kernel(const float* __restrict__ x,
                          const float* __restrict__ gw,
                          const float* __restrict__ gb) {
    int bg = blockIdx.x;
    int b = bg >> 5, g = bg & 31;
    const float* xp = x + ((size_t)b * CC + (size_t)g * CPG) * LL;
    float* hp = g_h + ((size_t)b * CC + (size_t)g * CPG) * LL;

    float s = 0.f, ss = 0.f;
    for (int i = threadIdx.x; i < CPG * LL; i += blockDim.x) {
        float v = xp[i];
        s += v;
        ss += v * v;
    }
    __shared__ float r0[256], r1[256];
    r0[threadIdx.x] = s;
    r1[threadIdx.x] = ss;
    __syncthreads();
    for (int o = 128; o > 0; o >>= 1) {
        if (threadIdx.x < o) {
            r0[threadIdx.x] += r0[threadIdx.x + o];
            r1[threadIdx.x] += r1[threadIdx.x + o];
        }
        __syncthreads();
    }
    const float invN = 1.f / (CPG * LL);
    float mean = r0[0] * invN;
    float var = r1[0] * invN - mean * mean;
    float rstd = rsqrtf(var + 1e-5f);

    for (int i = threadIdx.x; i < CPG * LL; i += blockDim.x) {
        int c = g * CPG + (i >> 10);
        hp[i] = (xp[i] - mean) * rstd * gw[c] + gb[c];
    }
}

// ---------------------------------------------------------------------------
// Kernel 2: QKV 1x1 conv as batched SGEMM.
// qkv[b][o][l] = sum_c W[o][c] * h[b][c][l] + bias[o]
// 64x64 output tile, K-step 16, 16x16 threads, 4x4 per thread (strided layout).
// ---------------------------------------------------------------------------
__global__ void qkv_gemm_kernel(const float* __restrict__ W,
                                const float* __restrict__ bias) {
    __shared__ float Ws[64 * 16];      // Ws[o_local * 16 + kk]
    __shared__ float Hs[16 * 64];      // Hs[kk * 64 + l_local]

    int b = blockIdx.z;
    int o0 = blockIdx.y * 64;
    int l0 = blockIdx.x * 64;
    int tx = threadIdx.x;  // 0..15  -> l
    int ty = threadIdx.y;  // 0..15  -> o
    int t = ty * 16 + tx;

    const float* hB = g_h + (size_t)b * CC * LL;
    float* qkvB = g_qkv + (size_t)b * 3 * CC * LL;

    float acc[4][4];
#pragma unroll
    for (int i = 0; i < 4; i++)
#pragma unroll
        for (int j = 0; j < 4; j++) acc[i][j] = 0.f;

    for (int k0 = 0; k0 < CC; k0 += 16) {
        // load W tile: [64 o][16 k]
#pragma unroll
        for (int i = t; i < 64 * 16; i += 256) {
            int o = i >> 4, kk = i & 15;
            Ws[o * 16 + kk] = W[(size_t)(o0 + o) * CC + k0 + kk];
        }
        // load H tile: [16 k][64 l]
#pragma unroll
        for (int i = t; i < 16 * 64; i += 256) {
            int kk = i >> 6, l = i & 63;
            Hs[kk * 64 + l] = hB[(size_t)(k0 + kk) * LL + l0 + l];
        }
        __syncthreads();

#pragma unroll
        for (int kk = 0; kk < 16; kk++) {
            float a[4], bv[4];
#pragma unroll
            for (int i = 0; i < 4; i++) a[i] = Ws[(ty + 16 * i) * 16 + kk];
#pragma unroll
            for (int j = 0; j < 4; j++) bv[j] = Hs[kk * 64 + tx + 16 * j];
#pragma unroll
            for (int i = 0; i < 4; i++)
#pragma unroll
                for (int j = 0; j < 4; j++) acc[i][j] += a[i] * bv[j];
        }
        __syncthreads();
    }

#pragma unroll
    for (int i = 0; i < 4; i++) {
        int o = o0 + ty + 16 * i;
        float bo = bias[o];
#pragma unroll
        for (int j = 0; j < 4; j++) {
            int l = l0 + tx + 16 * j;
            qkvB[(size_t)o * LL + l] = acc[i][j] + bo;
        }
    }
}

// ---------------------------------------------------------------------------
// Kernel 3: attention. One block per (bh, 16-query tile).
// S[16][1024] kept in shared, softmax in shared, then A = P * V^T.
// Output written fused with residual: out = x + a.
// ---------------------------------------------------------------------------
#define ATTN_SMEM_FLOATS (64 * 16 + 64 * 65 + 16 * 1025)

__global__ void attn_kernel(const float* __restrict__ x,
                            float* __restrict__ out) {
    extern __shared__ float sm[];
    float* Qs = sm;                 // [ch][q]  stride 16
    float* KVs = Qs + 64 * 16;      // [ch][s]  stride 65 (K, then reused for V)
    float* Ss = KVs + 64 * 65;      // [q][s]   stride 1025

    int q0 = blockIdx.x;            // 0..63 (16 queries each)
    int bh = blockIdx.y;            // 0..127
    int b = bh >> 3;
    int head = bh & 7;
    int t = threadIdx.x;

    const float* qptr = g_qkv + ((size_t)b * 3 * CC + (size_t)head * CHH) * LL;
    const float* kptr = qptr + (size_t)CC * LL;
    const float* vptr = qptr + (size_t)2 * CC * LL;

    // load Q tile [64 ch][16 q]
    for (int i = t; i < CHH * 16; i += 256) {
        int ch = i >> 4, qq = i & 15;
        Qs[ch * 16 + qq] = qptr[(size_t)ch * LL + q0 * 16 + qq];
    }
    __syncthreads();

    // ---- Phase A: scores ----
    {
        int q = t & 15;
        int sb = (t >> 4) * 4;
        for (int s0 = 0; s0 < LL; s0 += 64) {
            for (int i = t; i < CHH * 64; i += 256) {
                int ch = i >> 6, s = i & 63;
                KVs[ch * 65 + s] = kptr[(size_t)ch * LL + s0 + s];
            }
            __syncthreads();
            float a0 = 0.f, a1 = 0.f, a2 = 0.f, a3 = 0.f;
#pragma unroll
            for (int ch = 0; ch < CHH; ch++) {
                float qv = Qs[ch * 16 + q];
                const float* kr = &KVs[ch * 65 + sb];
                a0 += qv * kr[0];
                a1 += qv * kr[1];
                a2 += qv * kr[2];
                a3 += qv * kr[3];
            }
            float* sr = &Ss[q * 1025 + s0 + sb];
            sr[0] = a0 * 0.125f;
            sr[1] = a1 * 0.125f;
            sr[2] = a2 * 0.125f;
            sr[3] = a3 * 0.125f;
            __syncthreads();
        }
    }

    // ---- Softmax: 8 warps, 2 rows each ----
    {
        int warp = t >> 5, lane = t & 31;
        for (int qq = warp; qq < 16; qq += 8) {
            float* row = &Ss[qq * 1025];
            float m = -INFINITY;
            for (int s = lane; s < LL; s += 32) m = fmaxf(m, row[s]);
#pragma unroll
            for (int o = 16; o > 0; o >>= 1)
                m = fmaxf(m, __shfl_xor_sync(0xffffffffu, m, o));
            float sum = 0.f;
            for (int s = lane; s < LL; s += 32) {
                float e = __expf(row[s] - m);
                row[s] = e;
                sum += e;
            }
#pragma unroll
            for (int o = 16; o > 0; o >>= 1)
                sum += __shfl_xor_sync(0xffffffffu, sum, o);
            float inv = 1.f / sum;
            for (int s = lane; s < LL; s += 32) row[s] *= inv;
        }
    }
    __syncthreads();

    // ---- Phase B: A = P @ V^T ----
    {
        int q = t & 15;
        int ch0 = (t >> 4) * 4;
        float a0 = 0.f, a1 = 0.f, a2 = 0.f, a3 = 0.f;
        for (int s0 = 0; s0 < LL; s0 += 64) {
            for (int i = t; i < CHH * 64; i += 256) {
                int ch = i >> 6, s = i & 63;
                KVs[ch * 65 + s] = vptr[(size_t)ch * LL + s0 + s];
            }
            __syncthreads();
            const float* prow = &Ss[q * 1025 + s0];
#pragma unroll 8
            for (int s = 0; s < 64; s++) {
                float p = prow[s];
                a0 += p * KVs[(ch0 + 0) * 65 + s];
                a1 += p * KVs[(ch0 + 1) * 65 + s];
                a2 += p * KVs[(ch0 + 2) * 65 + s];
                a3 += p * KVs[(ch0 + 3) * 65 + s];
            }
            __syncthreads();
        }
        int c = head * CHH + ch0;
        int l = q0 * 16 + q;
        size_t base = ((size_t)b * CC + c) * LL + l;
        out[base + 0 * LL] = x[base + 0 * LL] + a0;
        out[base + 1 * LL] = x[base + 1 * LL] + a1;
        out[base + 2 * LL] = x[base + 2 * LL] + a2;
        out[base + 3 * LL] = x[base + 3 * LL] + a3;
    }
}

// ---------------------------------------------------------------------------
extern "C" void kernel_launch(void* const* d_in, const int* in_sizes, int n_in,
                              void* d_out, int out_size) {
    const float* x = (const float*)d_in[0];
    const float* gn_w = (const float*)d_in[1];
    const float* gn_b = (const float*)d_in[2];
    const float* conv_w = (const float*)d_in[3];
    const float* conv_b = (const float*)d_in[4];
    float* out = (float*)d_out;

    gn_kernel<<<BB * GG, 256>>>(x, gn_w, gn_b);

    dim3 gemm_grid(LL / 64, (3 * CC) / 64, BB);
    dim3 gemm_block(16, 16);
    qkv_gemm_kernel<<<gemm_grid, gemm_block>>>(conv_w, conv_b);

    size_t attn_smem = ATTN_SMEM_FLOATS * sizeof(float);
    cudaFuncSetAttribute(attn_kernel,
                         cudaFuncAttributeMaxDynamicSharedMemorySize,
                         (int)attn_smem);
    dim3 attn_grid(LL / 16, BB * HEADS);
    attn_kernel<<<attn_grid, 256, attn_smem>>>(x, out);
}

// round 2
// speedup vs baseline: 2.9556x; 2.9556x over previous
#include <cuda_runtime.h>
#include <math.h>

#define BB 16
#define CC 512
#define LL 1024
#define GG 32
#define CPG 16
#define HEADS 8
#define CHH 64

// Scratch (no allocation allowed): h (32MB), qkv (96MB)
__device__ float g_h[BB * CC * LL];
__device__ float g_qkv[BB * 3 * CC * LL];

__device__ __forceinline__ float to_tf32(float x) {
    float r;
    asm("cvt.rna.tf32.f32 %0, %1;" : "=f"(r) : "f"(x));
    return r;
}

__device__ __forceinline__ void mma_tf32(float d[4], const float a[4], const float b[2]) {
    asm volatile(
        "mma.sync.aligned.m16n8k8.row.col.f32.tf32.tf32.f32 "
        "{%0,%1,%2,%3}, {%4,%5,%6,%7}, {%8,%9}, {%0,%1,%2,%3};"
        : "+f"(d[0]), "+f"(d[1]), "+f"(d[2]), "+f"(d[3])
        : "r"(__float_as_uint(a[0])), "r"(__float_as_uint(a[1])),
          "r"(__float_as_uint(a[2])), "r"(__float_as_uint(a[3])),
          "r"(__float_as_uint(b[0])), "r"(__float_as_uint(b[1])));
}

// ---------------------------------------------------------------------------
// Kernel 1: GroupNorm(32).  One block per (b, g). Vectorized float4.
// ---------------------------------------------------------------------------
__global__ void gn_kernel(const float* __restrict__ x,
                          const float* __restrict__ gw,
                          const float* __restrict__ gb) {
    int bg = blockIdx.x;
    int b = bg >> 5, g = bg & 31;
    const float* xp = x + ((size_t)b * CC + (size_t)g * CPG) * LL;
    float* hp = g_h + ((size_t)b * CC + (size_t)g * CPG) * LL;
    const float4* xp4 = (const float4*)xp;
    float4* hp4 = (float4*)hp;

    float s = 0.f, ss = 0.f;
    for (int i = threadIdx.x; i < CPG * LL / 4; i += blockDim.x) {
        float4 v = xp4[i];
        s += v.x + v.y + v.z + v.w;
        ss += v.x * v.x + v.y * v.y + v.z * v.z + v.w * v.w;
    }
    __shared__ float r0[256], r1[256];
    r0[threadIdx.x] = s;
    r1[threadIdx.x] = ss;
    __syncthreads();
    for (int o = 128; o > 0; o >>= 1) {
        if (threadIdx.x < o) {
            r0[threadIdx.x] += r0[threadIdx.x + o];
            r1[threadIdx.x] += r1[threadIdx.x + o];
        }
        __syncthreads();
    }
    const float invN = 1.f / (CPG * LL);
    float mean = r0[0] * invN;
    float var = r1[0] * invN - mean * mean;
    float rstd = rsqrtf(var + 1e-5f);

    for (int i = threadIdx.x; i < CPG * LL / 4; i += blockDim.x) {
        int c = g * CPG + ((i * 4) >> 10);
        float wv = gw[c] * rstd, bv = gb[c] - mean * wv;
        float4 v = xp4[i];
        v.x = v.x * wv + bv;
        v.y = v.y * wv + bv;
        v.z = v.z * wv + bv;
        v.w = v.w * wv + bv;
        hp4[i] = v;
    }
}

// ---------------------------------------------------------------------------
// Kernel 2: QKV 1x1 conv as batched GEMM on tensor cores (tf32 mma).
// Block tile 128(o) x 64(l), 8 warps (4x2), warp tile 32x32, K-chunk 16.
// ---------------------------------------------------------------------------
#define WS_STRIDE 20
#define HS_STRIDE 72

__global__ void __launch_bounds__(256) qkv_gemm_tc(const float* __restrict__ W,
                                                   const float* __restrict__ bias) {
    __shared__ float Ws[128 * WS_STRIDE];
    __shared__ float Hs[16 * HS_STRIDE];

    int b = blockIdx.z;
    int o0 = blockIdx.y * 128;
    int l0 = blockIdx.x * 64;
    int t = threadIdx.x;
    int warp = t >> 5, lane = t & 31;
    int wo = warp >> 1, wl = warp & 1;

    const float* hB = g_h + (size_t)b * CC * LL;
    float* qkvB = g_qkv + (size_t)b * 3 * CC * LL;

    float acc[2][4][4];
#pragma unroll
    for (int m = 0; m < 2; m++)
#pragma unroll
        for (int n = 0; n < 4; n++)
#pragma unroll
            for (int r = 0; r < 4; r++) acc[m][n][r] = 0.f;

    for (int k0 = 0; k0 < CC; k0 += 16) {
        // stage W tile [128 o][16 c] -> Ws (tf32)
        {
            int o = t >> 2, cq = (t & 3) * 4;
#pragma unroll
            for (int rep = 0; rep < 2; rep++) {
                float4 v = *(const float4*)(W + (size_t)(o0 + o) * CC + k0 + cq);
                v.x = to_tf32(v.x); v.y = to_tf32(v.y);
                v.z = to_tf32(v.z); v.w = to_tf32(v.w);
                *(float4*)&Ws[o * WS_STRIDE + cq] = v;
                o += 64;
            }
        }
        // stage H tile [16 c][64 l] -> Hs (tf32)
        {
            int c = t >> 4, lq = (t & 15) * 4;
            float4 v = *(const float4*)(hB + (size_t)(k0 + c) * LL + l0 + lq);
            v.x = to_tf32(v.x); v.y = to_tf32(v.y);
            v.z = to_tf32(v.z); v.w = to_tf32(v.w);
            *(float4*)&Hs[c * HS_STRIDE + lq] = v;
        }
        __syncthreads();

#pragma unroll
        for (int kk = 0; kk < 2; kk++) {
            float a[2][4], bf[4][2];
#pragma unroll
            for (int m = 0; m < 2; m++) {
                int row = wo * 32 + m * 16 + (lane >> 2);
                int col = kk * 8 + (lane & 3);
                a[m][0] = Ws[row * WS_STRIDE + col];
                a[m][1] = Ws[(row + 8) * WS_STRIDE + col];
                a[m][2] = Ws[row * WS_STRIDE + col + 4];
                a[m][3] = Ws[(row + 8) * WS_STRIDE + col + 4];
            }
#pragma unroll
            for (int n = 0; n < 4; n++) {
                int ncol = wl * 32 + n * 8 + (lane >> 2);
                int krow = kk * 8 + (lane & 3);
                bf[n][0] = Hs[krow * HS_STRIDE + ncol];
                bf[n][1] = Hs[(krow + 4) * HS_STRIDE + ncol];
            }
#pragma unroll
            for (int m = 0; m < 2; m++)
#pragma unroll
                for (int n = 0; n < 4; n++) mma_tf32(acc[m][n], a[m], bf[n]);
        }
        __syncthreads();
    }

    // epilogue
#pragma unroll
    for (int m = 0; m < 2; m++) {
        int o = o0 + wo * 32 + m * 16 + (lane >> 2);
        float b0 = bias[o], b1 = bias[o + 8];
#pragma unroll
        for (int n = 0; n < 4; n++) {
            int l = l0 + wl * 32 + n * 8 + 2 * (lane & 3);
            *(float2*)&qkvB[(size_t)o * LL + l] =
                make_float2(acc[m][n][0] + b0, acc[m][n][1] + b0);
            *(float2*)&qkvB[(size_t)(o + 8) * LL + l] =
                make_float2(acc[m][n][2] + b1, acc[m][n][3] + b1);
        }
    }
}

// ---------------------------------------------------------------------------
// Kernel 3: attention on tensor cores. Block = (bh, 32-query tile), 512 thr.
// S[32][1024] in shared (fp32), K/V staged 64-wide, tf32 mma both phases.
// ---------------------------------------------------------------------------
#define SS_STRIDE 1036
#define KV_STRIDE 68
#define ATTN_SMEM_FLOATS (32 * SS_STRIDE + 64 * KV_STRIDE)

__global__ void __launch_bounds__(512, 1) attn_tc(const float* __restrict__ x,
                                                  float* __restrict__ out) {
    extern __shared__ float sm[];
    float* Ss = sm;                       // [32 q][1036]
    float* KV = sm + 32 * SS_STRIDE;      // [64][68] K^T / V / Q staging

    int q0 = blockIdx.x;                  // 0..31 (32 queries each)
    int bh = blockIdx.y;                  // 0..127
    int b = bh >> 3, head = bh & 7;
    int t = threadIdx.x, warp = t >> 5, lane = t & 31;

    const float* qptr = g_qkv + ((size_t)b * 3 * CC + (size_t)head * CHH) * LL;
    const float* kptr = qptr + (size_t)CC * LL;
    const float* vptr = qptr + 2 * (size_t)CC * LL;

    // stage Q transposed: Qs[q][ch] (tf32), in KV buffer
    {
        int q = t & 31, chb = (t >> 5) * 4;
        float4 v;
        v.x = to_tf32(qptr[(size_t)(chb + 0) * LL + q0 * 32 + q]);
        v.y = to_tf32(qptr[(size_t)(chb + 1) * LL + q0 * 32 + q]);
        v.z = to_tf32(qptr[(size_t)(chb + 2) * LL + q0 * 32 + q]);
        v.w = to_tf32(qptr[(size_t)(chb + 3) * LL + q0 * 32 + q]);
        *(float4*)&KV[q * KV_STRIDE + chb] = v;
    }
    __syncthreads();

    int mh = warp >> 3;          // 0/1: q half
    int sub = warp & 7;          // s-column (phase A) / ch-column (phase B)
    int r0 = mh * 16 + (lane >> 2);

    // preload Q fragments (8 k-steps x 4 regs)
    float qa[8][4];
#pragma unroll
    for (int kk = 0; kk < 8; kk++) {
        int c = kk * 8 + (lane & 3);
        qa[kk][0] = KV[r0 * KV_STRIDE + c];
        qa[kk][1] = KV[(r0 + 8) * KV_STRIDE + c];
        qa[kk][2] = KV[r0 * KV_STRIDE + c + 4];
        qa[kk][3] = KV[(r0 + 8) * KV_STRIDE + c + 4];
    }
    __syncthreads();

    // ---- Phase A: S = Q K^T * scale ----
    for (int s0 = 0; s0 < LL; s0 += 64) {
        // stage K transposed: Ks[s][ch] (tf32)
        {
            int s = t & 63, chb = (t >> 6) * 8;
#pragma unroll
            for (int g = 0; g < 2; g++) {
                int c = chb + g * 4;
                float4 v;
                v.x = to_tf32(kptr[(size_t)(c + 0) * LL + s0 + s]);
                v.y = to_tf32(kptr[(size_t)(c + 1) * LL + s0 + s]);
                v.z = to_tf32(kptr[(size_t)(c + 2) * LL + s0 + s]);
                v.w = to_tf32(kptr[(size_t)(c + 3) * LL + s0 + s]);
                *(float4*)&KV[s * KV_STRIDE + c] = v;
            }
        }
        __syncthreads();

        float d[4] = {0.f, 0.f, 0.f, 0.f};
        int srow = sub * 8 + (lane >> 2);
#pragma unroll
        for (int kk = 0; kk < 8; kk++) {
            float bf[2];
            int c = kk * 8 + (lane & 3);
            bf[0] = KV[srow * KV_STRIDE + c];
            bf[1] = KV[srow * KV_STRIDE + c + 4];
            mma_tf32(d, qa[kk], bf);
        }
        int sa = s0 + sub * 8 + 2 * (lane & 3);
        *(float2*)&Ss[r0 * SS_STRIDE + sa] = make_float2(d[0] * 0.125f, d[1] * 0.125f);
        *(float2*)&Ss[(r0 + 8) * SS_STRIDE + sa] = make_float2(d[2] * 0.125f, d[3] * 0.125f);
        __syncthreads();
    }

    // ---- Softmax: 16 warps x 2 rows; final values rounded to tf32 ----
#pragma unroll
    for (int rr = 0; rr < 2; rr++) {
        int q = warp * 2 + rr;
        float* row = &Ss[q * SS_STRIDE];
        float m = -INFINITY;
        for (int s = lane; s < LL; s += 32) m = fmaxf(m, row[s]);
#pragma unroll
        for (int o = 16; o > 0; o >>= 1)
            m = fmaxf(m, __shfl_xor_sync(0xffffffffu, m, o));
        float sum = 0.f;
        for (int s = lane; s < LL; s += 32) {
            float e = __expf(row[s] - m);
            row[s] = e;
            sum += e;
        }
#pragma unroll
        for (int o = 16; o > 0; o >>= 1)
            sum += __shfl_xor_sync(0xffffffffu, sum, o);
        float inv = 1.f / sum;
        for (int s = lane; s < LL; s += 32) row[s] = to_tf32(row[s] * inv);
    }
    __syncthreads();

    // ---- Phase B: A = P V^T ----
    float d[4] = {0.f, 0.f, 0.f, 0.f};
    for (int s0 = 0; s0 < LL; s0 += 64) {
        // stage V: Vs[ch][s] (tf32)
        {
            int ch = t >> 3, sg = (t & 7) * 8;
#pragma unroll
            for (int g = 0; g < 2; g++) {
                float4 v = *(const float4*)(vptr + (size_t)ch * LL + s0 + sg + g * 4);
                v.x = to_tf32(v.x); v.y = to_tf32(v.y);
                v.z = to_tf32(v.z); v.w = to_tf32(v.w);
                *(float4*)&KV[ch * KV_STRIDE + sg + g * 4] = v;
            }
        }
        __syncthreads();

        int chrow = sub * 8 + (lane >> 2);
#pragma unroll
        for (int kk = 0; kk < 8; kk++) {
            float a[4], bf[2];
            int s = s0 + kk * 8 + (lane & 3);
            a[0] = Ss[r0 * SS_STRIDE + s];
            a[1] = Ss[(r0 + 8) * SS_STRIDE + s];
            a[2] = Ss[r0 * SS_STRIDE + s + 4];
            a[3] = Ss[(r0 + 8) * SS_STRIDE + s + 4];
            int sc = kk * 8 + (lane & 3);
            bf[0] = KV[chrow * KV_STRIDE + sc];
            bf[1] = KV[chrow * KV_STRIDE + sc + 4];
            mma_tf32(d, a, bf);
        }
        __syncthreads();
    }

    // epilogue: out = x + a  (fused residual)
    {
        int ch = head * CHH + sub * 8 + 2 * (lane & 3);
        int l = q0 * 32 + r0;
        size_t cb0 = ((size_t)b * CC + ch) * (size_t)LL;
        size_t cb1 = cb0 + LL;  // ch+1
        out[cb0 + l] = x[cb0 + l] + d[0];
        out[cb1 + l] = x[cb1 + l] + d[1];
        out[cb0 + l + 8] = x[cb0 + l + 8] + d[2];
        out[cb1 + l + 8] = x[cb1 + l + 8] + d[3];
    }
}

// ---------------------------------------------------------------------------
extern "C" void kernel_launch(void* const* d_in, const int* in_sizes, int n_in,
                              void* d_out, int out_size) {
    const float* x = (const float*)d_in[0];
    const float* gn_w = (const float*)d_in[1];
    const float* gn_b = (const float*)d_in[2];
    const float* conv_w = (const float*)d_in[3];
    const float* conv_b = (const float*)d_in[4];
    float* out = (float*)d_out;

    gn_kernel<<<BB * GG, 256>>>(x, gn_w, gn_b);

    dim3 gemm_grid(LL / 64, (3 * CC) / 128, BB);
    qkv_gemm_tc<<<gemm_grid, 256>>>(conv_w, conv_b);

    size_t attn_smem = ATTN_SMEM_FLOATS * sizeof(float);
    cudaFuncSetAttribute(attn_tc, cudaFuncAttributeMaxDynamicSharedMemorySize,
                         (int)attn_smem);
    dim3 attn_grid(LL / 32, BB * HEADS);
    attn_tc<<<attn_grid, 512, attn_smem>>>(x, out);
}

// round 4
// speedup vs baseline: 4.2308x; 1.4315x over previous
#include <cuda_runtime.h>
#include <cstdint>
#include <math.h>

#define BB 16
#define CC 512
#define LL 1024
#define GG 32
#define CPG 16
#define HEADS 8
#define CHH 64

// Scratch (no allocation allowed): h (32MB), qkv (96MB)
__device__ float g_h[BB * CC * LL];
__device__ float g_qkv[BB * 3 * CC * LL];

__device__ __forceinline__ float to_tf32(float x) {
    float r;
    asm("cvt.rna.tf32.f32 %0, %1;" : "=f"(r) : "f"(x));
    return r;
}

__device__ __forceinline__ void mma_tf32(float d[4], const float a[4], const float b[2]) {
    asm volatile(
        "mma.sync.aligned.m16n8k8.row.col.f32.tf32.tf32.f32 "
        "{%0,%1,%2,%3}, {%4,%5,%6,%7}, {%8,%9}, {%0,%1,%2,%3};"
        : "+f"(d[0]), "+f"(d[1]), "+f"(d[2]), "+f"(d[3])
        : "r"(__float_as_uint(a[0])), "r"(__float_as_uint(a[1])),
          "r"(__float_as_uint(a[2])), "r"(__float_as_uint(a[3])),
          "r"(__float_as_uint(b[0])), "r"(__float_as_uint(b[1])));
}

__device__ __forceinline__ void cp16(float* dst_smem, const float* src) {
    unsigned d = (unsigned)__cvta_generic_to_shared(dst_smem);
    asm volatile("cp.async.cg.shared.global [%0], [%1], 16;" :: "r"(d), "l"(src));
}
__device__ __forceinline__ void cp_commit() {
    asm volatile("cp.async.commit_group;");
}
__device__ __forceinline__ void cp_wait1() {
    asm volatile("cp.async.wait_group 1;");
}
__device__ __forceinline__ void cp_wait0() {
    asm volatile("cp.async.wait_group 0;");
}

// ---------------------------------------------------------------------------
// Kernel 1: GroupNorm(32).  One block per (b, g). Vectorized float4.
// ---------------------------------------------------------------------------
__global__ void gn_kernel(const float* __restrict__ x,
                          const float* __restrict__ gw,
                          const float* __restrict__ gb) {
    int bg = blockIdx.x;
    int b = bg >> 5, g = bg & 31;
    const float* xp = x + ((size_t)b * CC + (size_t)g * CPG) * LL;
    float* hp = g_h + ((size_t)b * CC + (size_t)g * CPG) * LL;
    const float4* xp4 = (const float4*)xp;
    float4* hp4 = (float4*)hp;

    float s = 0.f, ss = 0.f;
    for (int i = threadIdx.x; i < CPG * LL / 4; i += blockDim.x) {
        float4 v = xp4[i];
        s += v.x + v.y + v.z + v.w;
        ss += v.x * v.x + v.y * v.y + v.z * v.z + v.w * v.w;
    }
    __shared__ float r0[256], r1[256];
    r0[threadIdx.x] = s;
    r1[threadIdx.x] = ss;
    __syncthreads();
    for (int o = 128; o > 0; o >>= 1) {
        if (threadIdx.x < o) {
            r0[threadIdx.x] += r0[threadIdx.x + o];
            r1[threadIdx.x] += r1[threadIdx.x + o];
        }
        __syncthreads();
    }
    const float invN = 1.f / (CPG * LL);
    float mean = r0[0] * invN;
    float var = r1[0] * invN - mean * mean;
    float rstd = rsqrtf(var + 1e-5f);

    for (int i = threadIdx.x; i < CPG * LL / 4; i += blockDim.x) {
        int c = g * CPG + ((i * 4) >> 10);
        float wv = gw[c] * rstd, bv = gb[c] - mean * wv;
        float4 v = xp4[i];
        v.x = v.x * wv + bv;
        v.y = v.y * wv + bv;
        v.z = v.z * wv + bv;
        v.w = v.w * wv + bv;
        hp4[i] = v;
    }
}

// ---------------------------------------------------------------------------
// Kernel 2: QKV 1x1 conv, tensor cores + cp.async double buffering.
// Block tile 128(o) x 64(l), 8 warps (4x2), warp tile 32x32, K-chunk 16.
// ---------------------------------------------------------------------------
#define WS_STRIDE 20
#define HS_STRIDE 72

__global__ void __launch_bounds__(256) qkv_gemm_tc(const float* __restrict__ W,
                                                   const float* __restrict__ bias) {
    __shared__ float Ws[2][128 * WS_STRIDE];
    __shared__ float Hs[2][16 * HS_STRIDE];

    int b = blockIdx.z;
    int o0 = blockIdx.y * 128;
    int l0 = blockIdx.x * 64;
    int t = threadIdx.x;
    int warp = t >> 5, lane = t & 31;
    int wo = warp >> 1, wl = warp & 1;

    const float* hB = g_h + (size_t)b * CC * LL;
    float* qkvB = g_qkv + (size_t)b * 3 * CC * LL;

    // staging indices (raw fp32 via cp.async; cvt at fragment load)
    int wo_r0 = t >> 2, wc0 = (t & 3) * 4;        // W: 2 chunks per thread
    int hc = t >> 4, hl = (t & 15) * 4;           // H: 1 chunk per thread

    float acc[2][4][4];
#pragma unroll
    for (int m = 0; m < 2; m++)
#pragma unroll
        for (int n = 0; n < 4; n++)
#pragma unroll
            for (int r = 0; r < 4; r++) acc[m][n][r] = 0.f;

    // prologue: prefetch chunk 0
    {
        cp16(&Ws[0][wo_r0 * WS_STRIDE + wc0], W + (size_t)(o0 + wo_r0) * CC + wc0);
        cp16(&Ws[0][(wo_r0 + 64) * WS_STRIDE + wc0], W + (size_t)(o0 + wo_r0 + 64) * CC + wc0);
        cp16(&Hs[0][hc * HS_STRIDE + hl], hB + (size_t)hc * LL + l0 + hl);
        cp_commit();
    }

    const int NCHUNK = CC / 16;  // 32
    for (int ic = 0; ic < NCHUNK; ic++) {
        int cur = ic & 1;
        if (ic + 1 < NCHUNK) {
            int nxt = cur ^ 1;
            int k0 = (ic + 1) * 16;
            cp16(&Ws[nxt][wo_r0 * WS_STRIDE + wc0], W + (size_t)(o0 + wo_r0) * CC + k0 + wc0);
            cp16(&Ws[nxt][(wo_r0 + 64) * WS_STRIDE + wc0],
                 W + (size_t)(o0 + wo_r0 + 64) * CC + k0 + wc0);
            cp16(&Hs[nxt][hc * HS_STRIDE + hl], hB + (size_t)(k0 + hc) * LL + l0 + hl);
            cp_commit();
            cp_wait1();
        } else {
            cp_wait0();
        }
        __syncthreads();

#pragma unroll
        for (int kk = 0; kk < 2; kk++) {
            float a[2][4], bf[4][2];
#pragma unroll
            for (int m = 0; m < 2; m++) {
                int row = wo * 32 + m * 16 + (lane >> 2);
                int col = kk * 8 + (lane & 3);
                a[m][0] = to_tf32(Ws[cur][row * WS_STRIDE + col]);
                a[m][1] = to_tf32(Ws[cur][(row + 8) * WS_STRIDE + col]);
                a[m][2] = to_tf32(Ws[cur][row * WS_STRIDE + col + 4]);
                a[m][3] = to_tf32(Ws[cur][(row + 8) * WS_STRIDE + col + 4]);
            }
#pragma unroll
            for (int n = 0; n < 4; n++) {
                int ncol = wl * 32 + n * 8 + (lane >> 2);
                int krow = kk * 8 + (lane & 3);
                bf[n][0] = to_tf32(Hs[cur][krow * HS_STRIDE + ncol]);
                bf[n][1] = to_tf32(Hs[cur][(krow + 4) * HS_STRIDE + ncol]);
            }
#pragma unroll
            for (int m = 0; m < 2; m++)
#pragma unroll
                for (int n = 0; n < 4; n++) mma_tf32(acc[m][n], a[m], bf[n]);
        }
        __syncthreads();
    }

    // epilogue
#pragma unroll
    for (int m = 0; m < 2; m++) {
        int o = o0 + wo * 32 + m * 16 + (lane >> 2);
        float b0 = bias[o], b1 = bias[o + 8];
#pragma unroll
        for (int n = 0; n < 4; n++) {
            int l = l0 + wl * 32 + n * 8 + 2 * (lane & 3);
            *(float2*)&qkvB[(size_t)o * LL + l] =
                make_float2(acc[m][n][0] + b0, acc[m][n][1] + b0);
            *(float2*)&qkvB[(size_t)(o + 8) * LL + l] =
                make_float2(acc[m][n][2] + b1, acc[m][n][3] + b1);
        }
    }
}

// ---------------------------------------------------------------------------
// Kernel 3: attention, tensor cores + cp.async double-buffered K/V.
// Block = (bh, 32-query tile), 512 threads. K/V staged natural [ch][s].
// ---------------------------------------------------------------------------
#define SS_STRIDE 1036
#define KV_STRIDE 72
#define QS_STRIDE 68
#define AS_STRIDE 36
#define ATTN_SMEM_FLOATS (32 * SS_STRIDE + 2 * 64 * KV_STRIDE)

__global__ void __launch_bounds__(512, 1) attn_tc(const float* __restrict__ x,
                                                  float* __restrict__ out) {
    extern __shared__ float sm[];
    float* Ss = sm;                         // [32 q][1036]; also Q/A staging
    float* KV0 = sm + 32 * SS_STRIDE;       // [64 ch][72]
    float* KV1 = KV0 + 64 * KV_STRIDE;

    int q0 = blockIdx.x;                    // 0..31 (32 queries each)
    int bh = blockIdx.y;                    // 0..127
    int b = bh >> 3, head = bh & 7;
    int t = threadIdx.x, warp = t >> 5, lane = t & 31;

    const float* qptr = g_qkv + ((size_t)b * 3 * CC + (size_t)head * CHH) * LL;
    const float* kptr = qptr + (size_t)CC * LL;
    const float* vptr = qptr + 2 * (size_t)CC * LL;

    // staging indices: 1024 16B chunks per 64x64 tile, 2 per thread
    int sch0 = t >> 4, sof0 = (t & 15) * 4;          // chunk t
    int sch1 = (t + 512) >> 4, sof1 = ((t + 512) & 15) * 4;

    // prefetch K chunk 0 into KV0
    cp16(&KV0[sch0 * KV_STRIDE + sof0], kptr + (size_t)sch0 * LL + sof0);
    cp16(&KV0[sch1 * KV_STRIDE + sof1], kptr + (size_t)sch1 * LL + sof1);
    cp_commit();

    // stage Q transposed (raw): Qs[q][ch] in Ss area
    {
        int q = t & 31, chb = (t >> 5) * 4;
        float4 v;
        v.x = qptr[(size_t)(chb + 0) * LL + q0 * 32 + q];
        v.y = qptr[(size_t)(chb + 1) * LL + q0 * 32 + q];
        v.z = qptr[(size_t)(chb + 2) * LL + q0 * 32 + q];
        v.w = qptr[(size_t)(chb + 3) * LL + q0 * 32 + q];
        *(float4*)&Ss[q * QS_STRIDE + chb] = v;
    }
    __syncthreads();

    int mh = warp >> 3;          // 0/1: q half
    int sub = warp & 7;          // s-col group (A) / ch-col group (B)
    int r0 = mh * 16 + (lane >> 2);

    // preload Q fragments (8 k-steps x 4 regs), cvt once
    float qa[8][4];
#pragma unroll
    for (int kk = 0; kk < 8; kk++) {
        int c = kk * 8 + (lane & 3);
        qa[kk][0] = to_tf32(Ss[r0 * QS_STRIDE + c]);
        qa[kk][1] = to_tf32(Ss[(r0 + 8) * QS_STRIDE + c]);
        qa[kk][2] = to_tf32(Ss[r0 * QS_STRIDE + c + 4]);
        qa[kk][3] = to_tf32(Ss[(r0 + 8) * QS_STRIDE + c + 4]);
    }
    // loop-top syncthreads orders qa reads before score writes to Ss

    // ---- Phase A: S = Q K^T * scale ----
    for (int ic = 0; ic < 16; ic++) {
        float* cur = (ic & 1) ? KV1 : KV0;
        if (ic + 1 < 16) {
            float* nxt = (ic & 1) ? KV0 : KV1;
            int s0 = (ic + 1) * 64;
            cp16(&nxt[sch0 * KV_STRIDE + sof0], kptr + (size_t)sch0 * LL + s0 + sof0);
            cp16(&nxt[sch1 * KV_STRIDE + sof1], kptr + (size_t)sch1 * LL + s0 + sof1);
            cp_commit();
            cp_wait1();
        } else {
            cp_wait0();
        }
        __syncthreads();

        float d[4] = {0.f, 0.f, 0.f, 0.f};
        int sl = sub * 8 + (lane >> 2);  // local s within chunk
#pragma unroll
        for (int kk = 0; kk < 8; kk++) {
            float bf[2];
            int c = kk * 8 + (lane & 3);
            bf[0] = to_tf32(cur[c * KV_STRIDE + sl]);
            bf[1] = to_tf32(cur[(c + 4) * KV_STRIDE + sl]);
            mma_tf32(d, qa[kk], bf);
        }
        int sa = ic * 64 + sub * 8 + 2 * (lane & 3);
        *(float2*)&Ss[r0 * SS_STRIDE + sa] = make_float2(d[0] * 0.125f, d[1] * 0.125f);
        *(float2*)&Ss[(r0 + 8) * SS_STRIDE + sa] = make_float2(d[2] * 0.125f, d[3] * 0.125f);
        __syncthreads();
    }

    // prefetch V chunk 0 (overlaps softmax)
    cp16(&KV0[sch0 * KV_STRIDE + sof0], vptr + (size_t)sch0 * LL + sof0);
    cp16(&KV0[sch1 * KV_STRIDE + sof1], vptr + (size_t)sch1 * LL + sof1);
    cp_commit();

    // ---- Softmax: 16 warps x 2 rows; P rounded to tf32 ----
#pragma unroll
    for (int rr = 0; rr < 2; rr++) {
        int q = warp * 2 + rr;
        float* row = &Ss[q * SS_STRIDE];
        float m = -INFINITY;
        for (int s = lane; s < LL; s += 32) m = fmaxf(m, row[s]);
#pragma unroll
        for (int o = 16; o > 0; o >>= 1)
            m = fmaxf(m, __shfl_xor_sync(0xffffffffu, m, o));
        float sum = 0.f;
        for (int s = lane; s < LL; s += 32) {
            float e = __expf(row[s] - m);
            row[s] = e;
            sum += e;
        }
#pragma unroll
        for (int o = 16; o > 0; o >>= 1)
            sum += __shfl_xor_sync(0xffffffffu, sum, o);
        float inv = 1.f / sum;
        for (int s = lane; s < LL; s += 32) row[s] = to_tf32(row[s] * inv);
    }
    __syncthreads();

    // ---- Phase B: A = P V^T ----
    float d[4] = {0.f, 0.f, 0.f, 0.f};
    for (int ic = 0; ic < 16; ic++) {
        float* cur = (ic & 1) ? KV1 : KV0;
        if (ic + 1 < 16) {
            float* nxt = (ic & 1) ? KV0 : KV1;
            int s0 = (ic + 1) * 64;
            cp16(&nxt[sch0 * KV_STRIDE + sof0], vptr + (size_t)sch0 * LL + s0 + sof0);
            cp16(&nxt[sch1 * KV_STRIDE + sof1], vptr + (size_t)sch1 * LL + s0 + sof1);
            cp_commit();
            cp_wait1();
        } else {
            cp_wait0();
        }
        __syncthreads();

        int chl = sub * 8 + (lane >> 2);  // local out-channel
        int s0 = ic * 64;
#pragma unroll
        for (int kk = 0; kk < 8; kk++) {
            float a[4], bf[2];
            int s = s0 + kk * 8 + (lane & 3);
            a[0] = Ss[r0 * SS_STRIDE + s];
            a[1] = Ss[(r0 + 8) * SS_STRIDE + s];
            a[2] = Ss[r0 * SS_STRIDE + s + 4];
            a[3] = Ss[(r0 + 8) * SS_STRIDE + s + 4];
            int sc = kk * 8 + (lane & 3);
            bf[0] = to_tf32(cur[chl * KV_STRIDE + sc]);
            bf[1] = to_tf32(cur[chl * KV_STRIDE + sc + 4]);
            mma_tf32(d, a, bf);
        }
        __syncthreads();
    }

    // stage A tile [ch][q] into Ss, then coalesced residual-add stores
    {
        int ch = sub * 8 + 2 * (lane & 3);
        Ss[ch * AS_STRIDE + r0] = d[0];
        Ss[(ch + 1) * AS_STRIDE + r0] = d[1];
        Ss[ch * AS_STRIDE + r0 + 8] = d[2];
        Ss[(ch + 1) * AS_STRIDE + r0 + 8] = d[3];
    }
    __syncthreads();
    {
#pragma unroll
        for (int k = 0; k < 4; k++) {
            int idx = t + k * 512;
            int ch = idx >> 5, q = idx & 31;
            size_t gi = ((size_t)b * CC + head * CHH + ch) * LL + q0 * 32 + q;
            out[gi] = x[gi] + Ss[ch * AS_STRIDE + q];
        }
    }
}

// ---------------------------------------------------------------------------
extern "C" void kernel_launch(void* const* d_in, const int* in_sizes, int n_in,
                              void* d_out, int out_size) {
    const float* x = (const float*)d_in[0];
    const float* gn_w = (const float*)d_in[1];
    const float* gn_b = (const float*)d_in[2];
    const float* conv_w = (const float*)d_in[3];
    const float* conv_b = (const float*)d_in[4];
    float* out = (float*)d_out;

    gn_kernel<<<BB * GG, 256>>>(x, gn_w, gn_b);

    dim3 gemm_grid(LL / 64, (3 * CC) / 128, BB);
    qkv_gemm_tc<<<gemm_grid, 256>>>(conv_w, conv_b);

    size_t attn_smem = ATTN_SMEM_FLOATS * sizeof(float);
    cudaFuncSetAttribute(attn_tc, cudaFuncAttributeMaxDynamicSharedMemorySize,
                         (int)attn_smem);
    dim3 attn_grid(LL / 32, BB * HEADS);
    attn_tc<<<attn_grid, 512, attn_smem>>>(x, out);
}

// round 5
// speedup vs baseline: 6.3737x; 1.5065x over previous
#include <cuda_runtime.h>
#include <cuda_fp16.h>
#include <cstdint>
#include <math.h>

#define BB 16
#define CC 512
#define LL 1024
#define GG 32
#define CPG 16
#define HEADS 8
#define CHH 64

// Scratch (no allocation allowed)
__device__ __half g_hT[BB * LL * CC];                 // h transposed [b][l][c], fp16
__device__ __half g_wh[3 * CC * CC];                  // conv weight fp16
__device__ __half g_qkT[BB * 2 * HEADS * LL * CHH];   // q,k transposed [b][sec][head][l][ch]
__device__ __half g_v[BB * CC * LL];                  // v natural [b][ch_global][l]

__device__ __forceinline__ void mma_f16(float d[4], const unsigned a[4], const unsigned b[2]) {
    asm volatile(
        "mma.sync.aligned.m16n8k16.row.col.f32.f16.f16.f32 "
        "{%0,%1,%2,%3}, {%4,%5,%6,%7}, {%8,%9}, {%0,%1,%2,%3};"
        : "+f"(d[0]), "+f"(d[1]), "+f"(d[2]), "+f"(d[3])
        : "r"(a[0]), "r"(a[1]), "r"(a[2]), "r"(a[3]),
          "r"(b[0]), "r"(b[1]));
}

__device__ __forceinline__ void cp16h(__half* dst_smem, const __half* src) {
    unsigned d = (unsigned)__cvta_generic_to_shared(dst_smem);
    asm volatile("cp.async.cg.shared.global [%0], [%1], 16;" :: "r"(d), "l"(src));
}
__device__ __forceinline__ void cp_commit() { asm volatile("cp.async.commit_group;"); }
__device__ __forceinline__ void cp_wait1() { asm volatile("cp.async.wait_group 1;"); }
__device__ __forceinline__ void cp_wait0() { asm volatile("cp.async.wait_group 0;"); }

// ---------------------------------------------------------------------------
// Kernel 0: convert conv weight to fp16.
// ---------------------------------------------------------------------------
__global__ void wconv_kernel(const float* __restrict__ W) {
    int i = blockIdx.x * 256 + threadIdx.x;  // over float2 units (3*512*512/2)
    float2 w = ((const float2*)W)[i];
    ((__half2*)g_wh)[i] = __floats2half2_rn(w.x, w.y);
}

// ---------------------------------------------------------------------------
// Kernel 1: GroupNorm(32) -> hT [b][l][c] fp16. One block per (b, g).
// ---------------------------------------------------------------------------
__global__ void gn_kernel(const float* __restrict__ x,
                          const float* __restrict__ gw,
                          const float* __restrict__ gb) {
    int bg = blockIdx.x;
    int b = bg >> 5, g = bg & 31;
    const float* xp = x + ((size_t)b * CC + (size_t)g * CPG) * LL;
    const float4* xp4 = (const float4*)xp;
    int t = threadIdx.x;

    float s = 0.f, ss = 0.f;
    for (int i = t; i < CPG * LL / 4; i += 256) {
        float4 v = xp4[i];
        s += v.x + v.y + v.z + v.w;
        ss += v.x * v.x + v.y * v.y + v.z * v.z + v.w * v.w;
    }
    __shared__ float r0[256], r1[256];
    r0[t] = s; r1[t] = ss;
    __syncthreads();
    for (int o = 128; o > 0; o >>= 1) {
        if (t < o) { r0[t] += r0[t + o]; r1[t] += r1[t + o]; }
        __syncthreads();
    }
    const float invN = 1.f / (CPG * LL);
    float mean = r0[0] * invN;
    float var = r1[0] * invN - mean * mean;
    float rstd = rsqrtf(var + 1e-5f);

    // per-thread fixed 8 channels (h = t&1 selects half of the 16-ch group)
    int h = t & 1;
    float wv[8], bv[8];
#pragma unroll
    for (int j = 0; j < 8; j++) {
        int cg = g * CPG + h * 8 + j;
        wv[j] = gw[cg] * rstd;
        bv[j] = gb[cg] - mean * wv[j];
    }

    for (int u = t; u < 2 * LL; u += 256) {
        int l = u >> 1;  // h = u&1 == t&1 (256 even stride)
        uint4 pack;
        __half2* ph = (__half2*)&pack;
#pragma unroll
        for (int j = 0; j < 4; j++) {
            float v0 = xp[(size_t)(h * 8 + 2 * j) * LL + l];
            float v1 = xp[(size_t)(h * 8 + 2 * j + 1) * LL + l];
            ph[j] = __floats2half2_rn(v0 * wv[2 * j] + bv[2 * j],
                                      v1 * wv[2 * j + 1] + bv[2 * j + 1]);
        }
        *(uint4*)(g_hT + ((size_t)b * LL + l) * CC + g * CPG + h * 8) = pack;
    }
}

// ---------------------------------------------------------------------------
// Kernel 2: unified QKV GEMM (fp16 HMMA, cp.async double-buffered).
// qk blocks: D[l][o] = sum_c hT[l][c] W[o][c]  -> q,k transposed [l][ch]
// v  blocks: D[o][l] = sum_c W[o][c] hT[l][c]  -> v natural [ch][l]
// Block tile 128(m) x 64(n), 8 warps (4x2), warp tile 32x32, K-chunk 32.
// ---------------------------------------------------------------------------
#define APAD 40

__global__ void __launch_bounds__(256) qkv_gemm(const float* __restrict__ bias) {
    __shared__ __half As[2][128 * APAD];
    __shared__ __half Bs[2][64 * APAD];

    int id = blockIdx.x;
    bool isqk = id < 2048;
    int b, o0, l0;
    const __half *Asrc, *Bsrc;
    if (isqk) {
        int lt = id & 7, ot = (id >> 3) & 15;
        b = id >> 7;
        l0 = lt * 128; o0 = ot * 64;
        Asrc = g_hT + ((size_t)b * LL + l0) * CC;
        Bsrc = g_wh + (size_t)o0 * CC;
    } else {
        int id2 = id - 2048;
        int lt = id2 & 15, ot = (id2 >> 4) & 3;
        b = id2 >> 6;
        l0 = lt * 64; o0 = ot * 128;
        Asrc = g_wh + (size_t)(2 * CC + o0) * CC;
        Bsrc = g_hT + ((size_t)b * LL + l0) * CC;
    }
    int t = threadIdx.x, warp = t >> 5, lane = t & 31;
    int g = lane >> 2, tt = lane & 3;
    int wm = warp >> 1, wn = warp & 1;

    int ar = t >> 2, ac = (t & 3) * 8;  // A staging: rows ar, ar+64
    // B staging: rows t>>2 (0..63), cols (t&3)*8  — same indices

    float acc[2][4][4];
#pragma unroll
    for (int m = 0; m < 2; m++)
#pragma unroll
        for (int n = 0; n < 4; n++)
#pragma unroll
            for (int r = 0; r < 4; r++) acc[m][n][r] = 0.f;

    cp16h(&As[0][ar * APAD + ac], Asrc + (size_t)ar * CC + ac);
    cp16h(&As[0][(ar + 64) * APAD + ac], Asrc + (size_t)(ar + 64) * CC + ac);
    cp16h(&Bs[0][ar * APAD + ac], Bsrc + (size_t)ar * CC + ac);
    cp_commit();

    for (int ic = 0; ic < 16; ic++) {
        int cur = ic & 1;
        if (ic + 1 < 16) {
            int nxt = cur ^ 1, c0 = (ic + 1) * 32;
            cp16h(&As[nxt][ar * APAD + ac], Asrc + (size_t)ar * CC + c0 + ac);
            cp16h(&As[nxt][(ar + 64) * APAD + ac], Asrc + (size_t)(ar + 64) * CC + c0 + ac);
            cp16h(&Bs[nxt][ar * APAD + ac], Bsrc + (size_t)ar * CC + c0 + ac);
            cp_commit();
            cp_wait1();
        } else {
            cp_wait0();
        }
        __syncthreads();

#pragma unroll
        for (int kk = 0; kk < 2; kk++) {
            unsigned a[2][4], bb[4][2];
#pragma unroll
            for (int mm = 0; mm < 2; mm++) {
                const __half* p = &As[cur][(wm * 32 + mm * 16 + g) * APAD + kk * 16 + 2 * tt];
                a[mm][0] = *(const unsigned*)p;
                a[mm][1] = *(const unsigned*)(p + 8 * APAD);
                a[mm][2] = *(const unsigned*)(p + 8);
                a[mm][3] = *(const unsigned*)(p + 8 * APAD + 8);
            }
#pragma unroll
            for (int nn = 0; nn < 4; nn++) {
                const __half* p = &Bs[cur][(wn * 32 + nn * 8 + g) * APAD + kk * 16 + 2 * tt];
                bb[nn][0] = *(const unsigned*)p;
                bb[nn][1] = *(const unsigned*)(p + 8);
            }
#pragma unroll
            for (int mm = 0; mm < 2; mm++)
#pragma unroll
                for (int nn = 0; nn < 4; nn++) mma_f16(acc[mm][nn], a[mm], bb[nn]);
        }
        __syncthreads();
    }

    if (isqk) {
        int sec = o0 >> 9, head = (o0 >> 6) & 7;
        __half* dst = g_qkT + (((size_t)b * 2 + sec) * 8 + head) * LL * CHH;
#pragma unroll
        for (int mm = 0; mm < 2; mm++) {
            int l = l0 + wm * 32 + mm * 16 + g;
#pragma unroll
            for (int nn = 0; nn < 4; nn++) {
                int ch = wn * 32 + nn * 8 + 2 * tt;
                float2 b2 = *(const float2*)&bias[o0 + ch];
                *(__half2*)&dst[(size_t)l * CHH + ch] =
                    __floats2half2_rn(acc[mm][nn][0] + b2.x, acc[mm][nn][1] + b2.y);
                *(__half2*)&dst[(size_t)(l + 8) * CHH + ch] =
                    __floats2half2_rn(acc[mm][nn][2] + b2.x, acc[mm][nn][3] + b2.y);
            }
        }
    } else {
        __half* dst = g_v + (size_t)b * CC * LL;
#pragma unroll
        for (int mm = 0; mm < 2; mm++) {
            int o = o0 + wm * 32 + mm * 16 + g;
            float b0 = bias[2 * CC + o], b1 = bias[2 * CC + o + 8];
#pragma unroll
            for (int nn = 0; nn < 4; nn++) {
                int l = l0 + wn * 32 + nn * 8 + 2 * tt;
                *(__half2*)&dst[(size_t)o * LL + l] =
                    __floats2half2_rn(acc[mm][nn][0] + b0, acc[mm][nn][1] + b0);
                *(__half2*)&dst[(size_t)(o + 8) * LL + l] =
                    __floats2half2_rn(acc[mm][nn][2] + b1, acc[mm][nn][3] + b1);
            }
        }
    }
}

// ---------------------------------------------------------------------------
// Kernel 3: attention (fp16 HMMA). Block = (bh, 32-query tile), 512 threads.
// Q,K in [l][ch] fp16; V in [ch][l] fp16; P in-place fp16 after softmax.
// ---------------------------------------------------------------------------
#define SS_STRIDE 1036
#define QK_PAD 72
#define SS_BYTES (32 * SS_STRIDE * 4)
#define QS_BYTES (32 * QK_PAD * 2)
#define KV_BYTES (64 * QK_PAD * 2)
#define ATTN_SMEM (SS_BYTES + QS_BYTES + 2 * KV_BYTES)
#define AS_STRIDE 36

__global__ void __launch_bounds__(512, 1) attn_tc(const float* __restrict__ x,
                                                  float* __restrict__ out) {
    extern __shared__ char smc[];
    float* Ss = (float*)smc;                                 // [32][1036] fp32 scores
    __half* Qs = (__half*)(smc + SS_BYTES);                  // [32][72] fp16
    __half* KV0 = (__half*)(smc + SS_BYTES + QS_BYTES);      // [64][72] fp16
    __half* KV1 = KV0 + 64 * QK_PAD;

    int q0 = blockIdx.x;                 // 0..31
    int bh = blockIdx.y;                 // 0..127
    int b = bh >> 3, head = bh & 7;
    int t = threadIdx.x, warp = t >> 5, lane = t & 31;
    int g = lane >> 2, tt = lane & 3;

    const __half* qbase = g_qkT + (((size_t)b * 2 + 0) * 8 + head) * LL * CHH;
    const __half* kbase = g_qkT + (((size_t)b * 2 + 1) * 8 + head) * LL * CHH;
    const __half* vbase = g_v + ((size_t)b * CC + head * CHH) * LL;

    // stage K chunk 0 + Q tile
    {
        int row = t >> 3, cc = (t & 7) * 8;
        cp16h(&KV0[row * QK_PAD + cc], kbase + (size_t)row * CHH + cc);
        if (t < 256) {
            int qr = t >> 3;
            cp16h(&Qs[qr * QK_PAD + cc], qbase + (size_t)(q0 * 32 + qr) * CHH + cc);
        }
        cp_commit();
    }
    cp_wait0();
    __syncthreads();

    int mh = warp >> 3;                  // q half
    int sub = warp & 7;                  // s/ch column group
    int qrow = mh * 16 + g;

    // preload Q fragments: 4 k16 steps x 4 regs
    unsigned qa[4][4];
#pragma unroll
    for (int kk = 0; kk < 4; kk++) {
        const __half* p = &Qs[qrow * QK_PAD + kk * 16 + 2 * tt];
        qa[kk][0] = *(const unsigned*)p;
        qa[kk][1] = *(const unsigned*)(p + 8 * QK_PAD);
        qa[kk][2] = *(const unsigned*)(p + 8);
        qa[kk][3] = *(const unsigned*)(p + 8 * QK_PAD + 8);
    }

    int srow = t >> 3, scc = (t & 7) * 8;  // K/V staging indices

    // ---- Phase A: S = Q K^T * 1/8 ----
    for (int ic = 0; ic < 16; ic++) {
        __half* cur = (ic & 1) ? KV1 : KV0;
        if (ic + 1 < 16) {
            __half* nxt = (ic & 1) ? KV0 : KV1;
            cp16h(&nxt[srow * QK_PAD + scc], kbase + (size_t)((ic + 1) * 64 + srow) * CHH + scc);
            cp_commit();
            cp_wait1();
        } else {
            cp_wait0();
        }
        __syncthreads();

        float d[4] = {0.f, 0.f, 0.f, 0.f};
        int sg = sub * 8 + g;
#pragma unroll
        for (int kk = 0; kk < 4; kk++) {
            unsigned bf[2];
            const __half* p = &cur[sg * QK_PAD + kk * 16 + 2 * tt];
            bf[0] = *(const unsigned*)p;
            bf[1] = *(const unsigned*)(p + 8);
            mma_f16(d, qa[kk], bf);
        }
        int sa = ic * 64 + sub * 8 + 2 * tt;
        *(float2*)&Ss[qrow * SS_STRIDE + sa] = make_float2(d[0] * 0.125f, d[1] * 0.125f);
        *(float2*)&Ss[(qrow + 8) * SS_STRIDE + sa] = make_float2(d[2] * 0.125f, d[3] * 0.125f);
        __syncthreads();
    }

    // prefetch V chunk 0 (overlaps softmax)
    cp16h(&KV0[srow * QK_PAD + scc], vbase + (size_t)srow * LL + scc);
    cp_commit();

    // ---- Softmax: 16 warps x 2 rows; P written in-place as fp16 ----
#pragma unroll
    for (int rr = 0; rr < 2; rr++) {
        int q = warp * 2 + rr;
        float* row = &Ss[q * SS_STRIDE];
        __half2* rowh = (__half2*)row;
        float m = -INFINITY;
#pragma unroll 4
        for (int i = 0; i < 16; i++) {
            float2 v = *(float2*)&row[i * 64 + 2 * lane];
            m = fmaxf(m, fmaxf(v.x, v.y));
        }
#pragma unroll
        for (int o = 16; o > 0; o >>= 1)
            m = fmaxf(m, __shfl_xor_sync(0xffffffffu, m, o));
        float sum = 0.f;
        for (int i = 0; i < 16; i++) {
            float2 v = *(float2*)&row[i * 64 + 2 * lane];
            float e0 = __expf(v.x - m), e1 = __expf(v.y - m);
            sum += e0 + e1;
            rowh[i * 32 + lane] = __floats2half2_rn(e0, e1);  // trailing in-place write
        }
#pragma unroll
        for (int o = 16; o > 0; o >>= 1)
            sum += __shfl_xor_sync(0xffffffffu, sum, o);
        float inv = 1.f / sum;
        for (int i = 0; i < 16; i++) {
            __half2 p = rowh[i * 32 + lane];
            float2 pf = __half22float2(p);
            rowh[i * 32 + lane] = __floats2half2_rn(pf.x * inv, pf.y * inv);
        }
    }
    __syncthreads();

    // ---- Phase B: A = P V^T ----
    float d[4] = {0.f, 0.f, 0.f, 0.f};
    const char* Pb = (const char*)Ss;  // fp16 rows, byte stride SS_STRIDE*4
    for (int ic = 0; ic < 16; ic++) {
        __half* cur = (ic & 1) ? KV1 : KV0;
        if (ic + 1 < 16) {
            __half* nxt = (ic & 1) ? KV0 : KV1;
            cp16h(&nxt[srow * QK_PAD + scc], vbase + (size_t)srow * LL + (ic + 1) * 64 + scc);
            cp_commit();
            cp_wait1();
        } else {
            cp_wait0();
        }
        __syncthreads();

        int chg = sub * 8 + g;
#pragma unroll
        for (int kk = 0; kk < 4; kk++) {
            unsigned a[4], bf[2];
            const char* p = Pb + (size_t)qrow * (SS_STRIDE * 4) + ic * 128 + kk * 32 + 4 * tt;
            a[0] = *(const unsigned*)p;
            a[1] = *(const unsigned*)(p + 8 * (SS_STRIDE * 4));
            a[2] = *(const unsigned*)(p + 16);
            a[3] = *(const unsigned*)(p + 8 * (SS_STRIDE * 4) + 16);
            const __half* pv = &cur[chg * QK_PAD + kk * 16 + 2 * tt];
            bf[0] = *(const unsigned*)pv;
            bf[1] = *(const unsigned*)(pv + 8);
            mma_f16(d, a, bf);
        }
        __syncthreads();
    }

    // stage A tile [ch][q] into Ss (fp32), then coalesced residual-add stores
    {
        float* AS = Ss;
        int ch = sub * 8 + 2 * tt;
        AS[ch * AS_STRIDE + qrow] = d[0];
        AS[(ch + 1) * AS_STRIDE + qrow] = d[1];
        AS[ch * AS_STRIDE + qrow + 8] = d[2];
        AS[(ch + 1) * AS_STRIDE + qrow + 8] = d[3];
    }
    __syncthreads();
    {
#pragma unroll
        for (int k = 0; k < 4; k++) {
            int idx = t + k * 512;
            int ch = idx >> 5, q = idx & 31;
            size_t gi = ((size_t)b * CC + head * CHH + ch) * LL + q0 * 32 + q;
            out[gi] = x[gi] + Ss[ch * AS_STRIDE + q];
        }
    }
}

// ---------------------------------------------------------------------------
extern "C" void kernel_launch(void* const* d_in, const int* in_sizes, int n_in,
                              void* d_out, int out_size) {
    const float* x = (const float*)d_in[0];
    const float* gn_w = (const float*)d_in[1];
    const float* gn_b = (const float*)d_in[2];
    const float* conv_w = (const float*)d_in[3];
    const float* conv_b = (const float*)d_in[4];
    float* out = (float*)d_out;

    wconv_kernel<<<3 * CC * CC / 512, 256>>>(conv_w);
    gn_kernel<<<BB * GG, 256>>>(x, gn_w, gn_b);
    qkv_gemm<<<3072, 256>>>(conv_b);

    cudaFuncSetAttribute(attn_tc, cudaFuncAttributeMaxDynamicSharedMemorySize,
                         ATTN_SMEM);
    dim3 attn_grid(LL / 32, BB * HEADS);
    attn_tc<<<attn_grid, 512, ATTN_SMEM>>>(x, out);
}

// round 6
// speedup vs baseline: 12.6073x; 1.9780x over previous
#include <cuda_runtime.h>
#include <cuda_fp16.h>
#include <cstdint>
#include <math.h>

#define BB 16
#define CC 512
#define LL 1024
#define GG 32
#define CPG 16
#define HEADS 8
#define CHH 64

// Scratch (no allocation allowed)
__device__ __half g_hT[BB * LL * CC];                 // h transposed [b][l][c], fp16
__device__ __half g_wh[3 * CC * CC];                  // conv weight fp16
__device__ __half g_qkT[BB * 2 * HEADS * LL * CHH];   // q,k transposed [b][sec][head][l][ch]
__device__ __half g_v[BB * CC * LL];                  // v natural [b][ch_global][l]

__device__ __forceinline__ void mma_f16(float d[4], const unsigned a[4], const unsigned b[2]) {
    asm volatile(
        "mma.sync.aligned.m16n8k16.row.col.f32.f16.f16.f32 "
        "{%0,%1,%2,%3}, {%4,%5,%6,%7}, {%8,%9}, {%0,%1,%2,%3};"
        : "+f"(d[0]), "+f"(d[1]), "+f"(d[2]), "+f"(d[3])
        : "r"(a[0]), "r"(a[1]), "r"(a[2]), "r"(a[3]),
          "r"(b[0]), "r"(b[1]));
}

__device__ __forceinline__ void cp16h(__half* dst_smem, const __half* src) {
    unsigned d = (unsigned)__cvta_generic_to_shared(dst_smem);
    asm volatile("cp.async.cg.shared.global [%0], [%1], 16;" :: "r"(d), "l"(src));
}
__device__ __forceinline__ void cp_commit() { asm volatile("cp.async.commit_group;"); }
__device__ __forceinline__ void cp_wait1() { asm volatile("cp.async.wait_group 1;"); }
__device__ __forceinline__ void cp_wait0() { asm volatile("cp.async.wait_group 0;"); }

// ---------------------------------------------------------------------------
// Kernel 0: convert conv weight to fp16.
// ---------------------------------------------------------------------------
__global__ void wconv_kernel(const float* __restrict__ W) {
    int i = blockIdx.x * 256 + threadIdx.x;
    float2 w = ((const float2*)W)[i];
    ((__half2*)g_wh)[i] = __floats2half2_rn(w.x, w.y);
}

// ---------------------------------------------------------------------------
// Kernel 1: GroupNorm(32) -> hT [b][l][c] fp16. One block per (b, g).
// ---------------------------------------------------------------------------
__global__ void gn_kernel(const float* __restrict__ x,
                          const float* __restrict__ gw,
                          const float* __restrict__ gb) {
    int bg = blockIdx.x;
    int b = bg >> 5, g = bg & 31;
    const float* xp = x + ((size_t)b * CC + (size_t)g * CPG) * LL;
    const float4* xp4 = (const float4*)xp;
    int t = threadIdx.x;

    float s = 0.f, ss = 0.f;
    for (int i = t; i < CPG * LL / 4; i += 256) {
        float4 v = xp4[i];
        s += v.x + v.y + v.z + v.w;
        ss += v.x * v.x + v.y * v.y + v.z * v.z + v.w * v.w;
    }
    __shared__ float r0[256], r1[256];
    r0[t] = s; r1[t] = ss;
    __syncthreads();
    for (int o = 128; o > 0; o >>= 1) {
        if (t < o) { r0[t] += r0[t + o]; r1[t] += r1[t + o]; }
        __syncthreads();
    }
    const float invN = 1.f / (CPG * LL);
    float mean = r0[0] * invN;
    float var = r1[0] * invN - mean * mean;
    float rstd = rsqrtf(var + 1e-5f);

    int h = t & 1;
    float wv[8], bv[8];
#pragma unroll
    for (int j = 0; j < 8; j++) {
        int cg = g * CPG + h * 8 + j;
        wv[j] = gw[cg] * rstd;
        bv[j] = gb[cg] - mean * wv[j];
    }

    for (int u = t; u < 2 * LL; u += 256) {
        int l = u >> 1;
        uint4 pack;
        __half2* ph = (__half2*)&pack;
#pragma unroll
        for (int j = 0; j < 4; j++) {
            float v0 = xp[(size_t)(h * 8 + 2 * j) * LL + l];
            float v1 = xp[(size_t)(h * 8 + 2 * j + 1) * LL + l];
            ph[j] = __floats2half2_rn(v0 * wv[2 * j] + bv[2 * j],
                                      v1 * wv[2 * j + 1] + bv[2 * j + 1]);
        }
        *(uint4*)(g_hT + ((size_t)b * LL + l) * CC + g * CPG + h * 8) = pack;
    }
}

// ---------------------------------------------------------------------------
// Kernel 2: unified QKV GEMM (fp16 HMMA, cp.async double-buffered).
// ---------------------------------------------------------------------------
#define APAD 40

__global__ void __launch_bounds__(256) qkv_gemm(const float* __restrict__ bias) {
    __shared__ __half As[2][128 * APAD];
    __shared__ __half Bs[2][64 * APAD];

    int id = blockIdx.x;
    bool isqk = id < 2048;
    int b, o0, l0;
    const __half *Asrc, *Bsrc;
    if (isqk) {
        int lt = id & 7, ot = (id >> 3) & 15;
        b = id >> 7;
        l0 = lt * 128; o0 = ot * 64;
        Asrc = g_hT + ((size_t)b * LL + l0) * CC;
        Bsrc = g_wh + (size_t)o0 * CC;
    } else {
        int id2 = id - 2048;
        int lt = id2 & 15, ot = (id2 >> 4) & 3;
        b = id2 >> 6;
        l0 = lt * 64; o0 = ot * 128;
        Asrc = g_wh + (size_t)(2 * CC + o0) * CC;
        Bsrc = g_hT + ((size_t)b * LL + l0) * CC;
    }
    int t = threadIdx.x, warp = t >> 5, lane = t & 31;
    int g = lane >> 2, tt = lane & 3;
    int wm = warp >> 1, wn = warp & 1;

    int ar = t >> 2, ac = (t & 3) * 8;

    float acc[2][4][4];
#pragma unroll
    for (int m = 0; m < 2; m++)
#pragma unroll
        for (int n = 0; n < 4; n++)
#pragma unroll
            for (int r = 0; r < 4; r++) acc[m][n][r] = 0.f;

    cp16h(&As[0][ar * APAD + ac], Asrc + (size_t)ar * CC + ac);
    cp16h(&As[0][(ar + 64) * APAD + ac], Asrc + (size_t)(ar + 64) * CC + ac);
    cp16h(&Bs[0][ar * APAD + ac], Bsrc + (size_t)ar * CC + ac);
    cp_commit();

    for (int ic = 0; ic < 16; ic++) {
        int cur = ic & 1;
        if (ic + 1 < 16) {
            int nxt = cur ^ 1, c0 = (ic + 1) * 32;
            cp16h(&As[nxt][ar * APAD + ac], Asrc + (size_t)ar * CC + c0 + ac);
            cp16h(&As[nxt][(ar + 64) * APAD + ac], Asrc + (size_t)(ar + 64) * CC + c0 + ac);
            cp16h(&Bs[nxt][ar * APAD + ac], Bsrc + (size_t)ar * CC + c0 + ac);
            cp_commit();
            cp_wait1();
        } else {
            cp_wait0();
        }
        __syncthreads();

#pragma unroll
        for (int kk = 0; kk < 2; kk++) {
            unsigned a[2][4], bb[4][2];
#pragma unroll
            for (int mm = 0; mm < 2; mm++) {
                const __half* p = &As[cur][(wm * 32 + mm * 16 + g) * APAD + kk * 16 + 2 * tt];
                a[mm][0] = *(const unsigned*)p;
                a[mm][1] = *(const unsigned*)(p + 8 * APAD);
                a[mm][2] = *(const unsigned*)(p + 8);
                a[mm][3] = *(const unsigned*)(p + 8 * APAD + 8);
            }
#pragma unroll
            for (int nn = 0; nn < 4; nn++) {
                const __half* p = &Bs[cur][(wn * 32 + nn * 8 + g) * APAD + kk * 16 + 2 * tt];
                bb[nn][0] = *(const unsigned*)p;
                bb[nn][1] = *(const unsigned*)(p + 8);
            }
#pragma unroll
            for (int mm = 0; mm < 2; mm++)
#pragma unroll
                for (int nn = 0; nn < 4; nn++) mma_f16(acc[mm][nn], a[mm], bb[nn]);
        }
        __syncthreads();
    }

    if (isqk) {
        int sec = o0 >> 9, head = (o0 >> 6) & 7;
        __half* dst = g_qkT + (((size_t)b * 2 + sec) * 8 + head) * LL * CHH;
#pragma unroll
        for (int mm = 0; mm < 2; mm++) {
            int l = l0 + wm * 32 + mm * 16 + g;
#pragma unroll
            for (int nn = 0; nn < 4; nn++) {
                int ch = wn * 32 + nn * 8 + 2 * tt;
                float2 b2 = *(const float2*)&bias[o0 + ch];
                *(__half2*)&dst[(size_t)l * CHH + ch] =
                    __floats2half2_rn(acc[mm][nn][0] + b2.x, acc[mm][nn][1] + b2.y);
                *(__half2*)&dst[(size_t)(l + 8) * CHH + ch] =
                    __floats2half2_rn(acc[mm][nn][2] + b2.x, acc[mm][nn][3] + b2.y);
            }
        }
    } else {
        __half* dst = g_v + (size_t)b * CC * LL;
#pragma unroll
        for (int mm = 0; mm < 2; mm++) {
            int o = o0 + wm * 32 + mm * 16 + g;
            float b0 = bias[2 * CC + o], b1 = bias[2 * CC + o + 8];
#pragma unroll
            for (int nn = 0; nn < 4; nn++) {
                int l = l0 + wn * 32 + nn * 8 + 2 * tt;
                *(__half2*)&dst[(size_t)o * LL + l] =
                    __floats2half2_rn(acc[mm][nn][0] + b0, acc[mm][nn][1] + b0);
                *(__half2*)&dst[(size_t)(o + 8) * LL + l] =
                    __floats2half2_rn(acc[mm][nn][2] + b1, acc[mm][nn][3] + b1);
            }
        }
    }
}

// ---------------------------------------------------------------------------
// Kernel 3: flash attention (fp16 HMMA, online softmax, 4 warps, 64-q tile).
// Q,K in [l][ch] fp16; V in [ch][l] fp16. P stays in registers.
// ---------------------------------------------------------------------------
#define FPAD 72
#define Q_BYTES (64 * FPAD * 2)
#define KVB_BYTES (64 * FPAD * 2)
#define FSMEM (Q_BYTES + 4 * KVB_BYTES)
#define AS_ST 68

__global__ void __launch_bounds__(128) attn_flash(const float* __restrict__ x,
                                                  float* __restrict__ out) {
    extern __shared__ char smc[];
    __half* Qs = (__half*)smc;
    __half* Kb[2] = {(__half*)(smc + Q_BYTES), (__half*)(smc + Q_BYTES + 2 * KVB_BYTES)};
    __half* Vb[2] = {(__half*)(smc + Q_BYTES + KVB_BYTES), (__half*)(smc + Q_BYTES + 3 * KVB_BYTES)};

    int q0 = blockIdx.x;                 // 0..15 (64 queries each)
    int bh = blockIdx.y;                 // 0..127
    int b = bh >> 3, head = bh & 7;
    int t = threadIdx.x, warp = t >> 5, lane = t & 31;
    int g = lane >> 2, tt = lane & 3;

    const __half* qbase = g_qkT + (((size_t)b * 2 + 0) * 8 + head) * LL * CHH;
    const __half* kbase = g_qkT + (((size_t)b * 2 + 1) * 8 + head) * LL * CHH;
    const __half* vbase = g_v + ((size_t)b * CC + head * CHH) * LL;

    // staging: 512 16B-chunks per 64x64 fp16 tile, 4 per thread
    int srow[4], scol[4];
#pragma unroll
    for (int i = 0; i < 4; i++) {
        int ck = t + i * 128;
        srow[i] = ck >> 3;
        scol[i] = (ck & 7) * 8;
    }

    // prologue: Q + chunk0 (group0), chunk1 (group1)
#pragma unroll
    for (int i = 0; i < 4; i++) {
        cp16h(&Qs[srow[i] * FPAD + scol[i]], qbase + (size_t)(q0 * 64 + srow[i]) * CHH + scol[i]);
        cp16h(&Kb[0][srow[i] * FPAD + scol[i]], kbase + (size_t)srow[i] * CHH + scol[i]);
        cp16h(&Vb[0][srow[i] * FPAD + scol[i]], vbase + (size_t)srow[i] * LL + scol[i]);
    }
    cp_commit();
#pragma unroll
    for (int i = 0; i < 4; i++) {
        cp16h(&Kb[1][srow[i] * FPAD + scol[i]], kbase + (size_t)(64 + srow[i]) * CHH + scol[i]);
        cp16h(&Vb[1][srow[i] * FPAD + scol[i]], vbase + (size_t)srow[i] * LL + 64 + scol[i]);
    }
    cp_commit();

    // online softmax state + output accumulators (per-thread rows g, g+8 of warp's 16)
    float m0 = -INFINITY, m1 = -INFINITY, l0 = 0.f, l1 = 0.f;
    float o[8][4];
#pragma unroll
    for (int j = 0; j < 8; j++)
#pragma unroll
        for (int r = 0; r < 4; r++) o[j][r] = 0.f;

    unsigned qa[4][4];
    bool qloaded = false;

    for (int ic = 0; ic < 16; ic++) {
        if (ic < 15) cp_wait1(); else cp_wait0();
        __syncthreads();

        if (!qloaded) {  // Q ready after first wait
            const __half* qp = &Qs[(warp * 16 + g) * FPAD];
#pragma unroll
            for (int kk = 0; kk < 4; kk++) {
                const __half* p = qp + kk * 16 + 2 * tt;
                qa[kk][0] = *(const unsigned*)p;
                qa[kk][1] = *(const unsigned*)(p + 8 * FPAD);
                qa[kk][2] = *(const unsigned*)(p + 8);
                qa[kk][3] = *(const unsigned*)(p + 8 * FPAD + 8);
            }
            qloaded = true;
        }

        __half* K = Kb[ic & 1];
        __half* V = Vb[ic & 1];

        // ---- S = Q K^T (16q x 64s per warp) ----
        float d[8][4];
#pragma unroll
        for (int j = 0; j < 8; j++) {
            d[j][0] = d[j][1] = d[j][2] = d[j][3] = 0.f;
            const __half* kp = &K[(j * 8 + g) * FPAD + 2 * tt];
#pragma unroll
            for (int kk = 0; kk < 4; kk++) {
                unsigned bf[2];
                bf[0] = *(const unsigned*)(kp + kk * 16);
                bf[1] = *(const unsigned*)(kp + kk * 16 + 8);
                mma_f16(d[j], qa[kk], bf);
            }
        }

        // ---- online softmax update ----
        float cm0 = -INFINITY, cm1 = -INFINITY;
#pragma unroll
        for (int j = 0; j < 8; j++) {
            cm0 = fmaxf(cm0, fmaxf(d[j][0], d[j][1]));
            cm1 = fmaxf(cm1, fmaxf(d[j][2], d[j][3]));
        }
        cm0 = fmaxf(cm0, __shfl_xor_sync(0xffffffffu, cm0, 1));
        cm0 = fmaxf(cm0, __shfl_xor_sync(0xffffffffu, cm0, 2));
        cm1 = fmaxf(cm1, __shfl_xor_sync(0xffffffffu, cm1, 1));
        cm1 = fmaxf(cm1, __shfl_xor_sync(0xffffffffu, cm1, 2));
        cm0 *= 0.125f; cm1 *= 0.125f;

        float mn0 = fmaxf(m0, cm0), mn1 = fmaxf(m1, cm1);
        float al0 = __expf(m0 - mn0), al1 = __expf(m1 - mn1);
        m0 = mn0; m1 = mn1;

        float rs0 = 0.f, rs1 = 0.f;
        unsigned p2[8][2];
#pragma unroll
        for (int j = 0; j < 8; j++) {
            float e0 = __expf(d[j][0] * 0.125f - m0);
            float e1 = __expf(d[j][1] * 0.125f - m0);
            float e2 = __expf(d[j][2] * 0.125f - m1);
            float e3 = __expf(d[j][3] * 0.125f - m1);
            rs0 += e0 + e1; rs1 += e2 + e3;
            __half2 h01 = __floats2half2_rn(e0, e1);
            __half2 h23 = __floats2half2_rn(e2, e3);
            p2[j][0] = *(unsigned*)&h01;
            p2[j][1] = *(unsigned*)&h23;
        }
        rs0 += __shfl_xor_sync(0xffffffffu, rs0, 1);
        rs0 += __shfl_xor_sync(0xffffffffu, rs0, 2);
        rs1 += __shfl_xor_sync(0xffffffffu, rs1, 1);
        rs1 += __shfl_xor_sync(0xffffffffu, rs1, 2);
        l0 = l0 * al0 + rs0;
        l1 = l1 * al1 + rs1;

#pragma unroll
        for (int j = 0; j < 8; j++) {
            o[j][0] *= al0; o[j][1] *= al0;
            o[j][2] *= al1; o[j][3] *= al1;
        }

        // ---- O += P V^T : A-fragments come straight from p2 ----
#pragma unroll
        for (int j = 0; j < 8; j++) {       // j = ch n-tile
            const __half* vp = &V[(j * 8 + g) * FPAD + 2 * tt];
#pragma unroll
            for (int kk = 0; kk < 4; kk++) {  // kk = s k16-tile
                unsigned a[4] = {p2[2 * kk][0], p2[2 * kk][1],
                                 p2[2 * kk + 1][0], p2[2 * kk + 1][1]};
                unsigned bf[2];
                bf[0] = *(const unsigned*)(vp + kk * 16);
                bf[1] = *(const unsigned*)(vp + kk * 16 + 8);
                mma_f16(o[j], a, bf);
            }
        }

        __syncthreads();
        if (ic + 2 < 16) {
            __half* Kn = Kb[ic & 1];
            __half* Vn = Vb[ic & 1];
            int s0 = (ic + 2) * 64;
#pragma unroll
            for (int i = 0; i < 4; i++) {
                cp16h(&Kn[srow[i] * FPAD + scol[i]], kbase + (size_t)(s0 + srow[i]) * CHH + scol[i]);
                cp16h(&Vn[srow[i] * FPAD + scol[i]], vbase + (size_t)srow[i] * LL + s0 + scol[i]);
            }
            cp_commit();
        }
    }

    // ---- epilogue: A[ch][q] staged in smem, coalesced residual-add ----
    float* AS = (float*)smc;  // 64 x 68 fp32 = 17.4KB (reuse)
    float inv0 = 1.f / l0, inv1 = 1.f / l1;
    int qg = warp * 16 + g;
#pragma unroll
    for (int j = 0; j < 8; j++) {
        int ch = j * 8 + 2 * tt;
        AS[ch * AS_ST + qg] = o[j][0] * inv0;
        AS[(ch + 1) * AS_ST + qg] = o[j][1] * inv0;
        AS[ch * AS_ST + qg + 8] = o[j][2] * inv1;
        AS[(ch + 1) * AS_ST + qg + 8] = o[j][3] * inv1;
    }
    __syncthreads();
#pragma unroll
    for (int k = 0; k < 32; k++) {
        int idx = t + k * 128;
        int ch = idx >> 6, q = idx & 63;
        size_t gi = ((size_t)b * CC + head * CHH + ch) * LL + q0 * 64 + q;
        out[gi] = x[gi] + AS[ch * AS_ST + q];
    }
}

// ---------------------------------------------------------------------------
extern "C" void kernel_launch(void* const* d_in, const int* in_sizes, int n_in,
                              void* d_out, int out_size) {
    const float* x = (const float*)d_in[0];
    const float* gn_w = (const float*)d_in[1];
    const float* gn_b = (const float*)d_in[2];
    const float* conv_w = (const float*)d_in[3];
    const float* conv_b = (const float*)d_in[4];
    float* out = (float*)d_out;

    wconv_kernel<<<3 * CC * CC / 512, 256>>>(conv_w);
    gn_kernel<<<BB * GG, 256>>>(x, gn_w, gn_b);
    qkv_gemm<<<3072, 256>>>(conv_b);

    cudaFuncSetAttribute(attn_flash, cudaFuncAttributeMaxDynamicSharedMemorySize,
                         FSMEM);
    dim3 attn_grid(LL / 64, BB * HEADS);
    attn_flash<<<attn_grid, 128, FSMEM>>>(x, out);
}

// round 7
// speedup vs baseline: 13.2444x; 1.0505x over previous
#include <cuda_runtime.h>
#include <cuda_fp16.h>
#include <cstdint>
#include <math.h>

#define BB 16
#define CC 512
#define LL 1024
#define GG 32
#define CPG 16
#define HEADS 8
#define CHH 64

// Scratch (no allocation allowed)
__device__ __half g_hT[BB * LL * CC];                 // h transposed [b][l][c], fp16
__device__ __half g_wh[3 * CC * CC];                  // conv weight fp16
__device__ __half g_qkT[BB * 2 * HEADS * LL * CHH];   // q,k transposed [b][sec][head][l][ch]; q pre-scaled by 1/8
__device__ __half g_v[BB * CC * LL];                  // v natural [b][ch_global][l]

__device__ __forceinline__ void mma_f16(float d[4], const unsigned a[4], const unsigned b[2]) {
    asm volatile(
        "mma.sync.aligned.m16n8k16.row.col.f32.f16.f16.f32 "
        "{%0,%1,%2,%3}, {%4,%5,%6,%7}, {%8,%9}, {%0,%1,%2,%3};"
        : "+f"(d[0]), "+f"(d[1]), "+f"(d[2]), "+f"(d[3])
        : "r"(a[0]), "r"(a[1]), "r"(a[2]), "r"(a[3]),
          "r"(b[0]), "r"(b[1]));
}

__device__ __forceinline__ void cp16h(__half* dst_smem, const __half* src) {
    unsigned d = (unsigned)__cvta_generic_to_shared(dst_smem);
    asm volatile("cp.async.cg.shared.global [%0], [%1], 16;" :: "r"(d), "l"(src));
}
__device__ __forceinline__ void cp_commit() { asm volatile("cp.async.commit_group;"); }
__device__ __forceinline__ void cp_wait1() { asm volatile("cp.async.wait_group 1;"); }
__device__ __forceinline__ void cp_wait0() { asm volatile("cp.async.wait_group 0;"); }

// ---------------------------------------------------------------------------
// Kernel 0: convert conv weight to fp16.
// ---------------------------------------------------------------------------
__global__ void wconv_kernel(const float* __restrict__ W) {
    int i = blockIdx.x * 256 + threadIdx.x;
    float2 w = ((const float2*)W)[i];
    ((__half2*)g_wh)[i] = __floats2half2_rn(w.x, w.y);
}

// ---------------------------------------------------------------------------
// Kernel 1: GroupNorm(32) -> hT [b][l][c] fp16. One block per (b, g).
// ---------------------------------------------------------------------------
__global__ void gn_kernel(const float* __restrict__ x,
                          const float* __restrict__ gw,
                          const float* __restrict__ gb) {
    int bg = blockIdx.x;
    int b = bg >> 5, g = bg & 31;
    const float* xp = x + ((size_t)b * CC + (size_t)g * CPG) * LL;
    const float4* xp4 = (const float4*)xp;
    int t = threadIdx.x;

    float s = 0.f, ss = 0.f;
    for (int i = t; i < CPG * LL / 4; i += 256) {
        float4 v = xp4[i];
        s += v.x + v.y + v.z + v.w;
        ss += v.x * v.x + v.y * v.y + v.z * v.z + v.w * v.w;
    }
    __shared__ float r0[256], r1[256];
    r0[t] = s; r1[t] = ss;
    __syncthreads();
    for (int o = 128; o > 0; o >>= 1) {
        if (t < o) { r0[t] += r0[t + o]; r1[t] += r1[t + o]; }
        __syncthreads();
    }
    const float invN = 1.f / (CPG * LL);
    float mean = r0[0] * invN;
    float var = r1[0] * invN - mean * mean;
    float rstd = rsqrtf(var + 1e-5f);

    int h = t & 1;
    float wv[8], bv[8];
#pragma unroll
    for (int j = 0; j < 8; j++) {
        int cg = g * CPG + h * 8 + j;
        wv[j] = gw[cg] * rstd;
        bv[j] = gb[cg] - mean * wv[j];
    }

    for (int u = t; u < 2 * LL; u += 256) {
        int l = u >> 1;
        uint4 pack;
        __half2* ph = (__half2*)&pack;
#pragma unroll
        for (int j = 0; j < 4; j++) {
            float v0 = xp[(size_t)(h * 8 + 2 * j) * LL + l];
            float v1 = xp[(size_t)(h * 8 + 2 * j + 1) * LL + l];
            ph[j] = __floats2half2_rn(v0 * wv[2 * j] + bv[2 * j],
                                      v1 * wv[2 * j + 1] + bv[2 * j + 1]);
        }
        *(uint4*)(g_hT + ((size_t)b * LL + l) * CC + g * CPG + h * 8) = pack;
    }
}

// ---------------------------------------------------------------------------
// Kernel 2: unified QKV GEMM, 128x128 block tiles (fp16 HMMA, cp.async).
// qk blocks: D[l][o]; v blocks: D[o][l]. Warp tile 64x32. Q scaled by 1/8.
// ---------------------------------------------------------------------------
#define APAD 40

__global__ void __launch_bounds__(256, 2) qkv_gemm(const float* __restrict__ bias) {
    __shared__ __half As[2][128 * APAD];
    __shared__ __half Bs[2][128 * APAD];

    int id = blockIdx.x;
    bool isqk = id < 1024;
    int b, o0, l0;
    const __half *Asrc, *Bsrc;
    if (isqk) {
        int r = id & 63;
        b = id >> 6;
        l0 = (r & 7) * 128; o0 = (r >> 3) * 128;
        Asrc = g_hT + ((size_t)b * LL + l0) * CC;
        Bsrc = g_wh + (size_t)o0 * CC;
    } else {
        int id2 = id - 1024;
        int r = id2 & 31;
        b = id2 >> 5;
        l0 = (r & 7) * 128; o0 = (r >> 3) * 128;
        Asrc = g_wh + (size_t)(2 * CC + o0) * CC;
        Bsrc = g_hT + ((size_t)b * LL + l0) * CC;
    }
    int t = threadIdx.x, warp = t >> 5, lane = t & 31;
    int g = lane >> 2, tt = lane & 3;
    int wm = warp >> 2, wn = warp & 3;   // 2 x 4 warps, warp tile 64x32

    int ar = t >> 2, ac = (t & 3) * 8;

    float acc[4][4][4];
#pragma unroll
    for (int m = 0; m < 4; m++)
#pragma unroll
        for (int n = 0; n < 4; n++)
#pragma unroll
            for (int r = 0; r < 4; r++) acc[m][n][r] = 0.f;

    cp16h(&As[0][ar * APAD + ac], Asrc + (size_t)ar * CC + ac);
    cp16h(&As[0][(ar + 64) * APAD + ac], Asrc + (size_t)(ar + 64) * CC + ac);
    cp16h(&Bs[0][ar * APAD + ac], Bsrc + (size_t)ar * CC + ac);
    cp16h(&Bs[0][(ar + 64) * APAD + ac], Bsrc + (size_t)(ar + 64) * CC + ac);
    cp_commit();

    for (int ic = 0; ic < 16; ic++) {
        int cur = ic & 1;
        if (ic + 1 < 16) {
            int nxt = cur ^ 1, c0 = (ic + 1) * 32;
            cp16h(&As[nxt][ar * APAD + ac], Asrc + (size_t)ar * CC + c0 + ac);
            cp16h(&As[nxt][(ar + 64) * APAD + ac], Asrc + (size_t)(ar + 64) * CC + c0 + ac);
            cp16h(&Bs[nxt][ar * APAD + ac], Bsrc + (size_t)ar * CC + c0 + ac);
            cp16h(&Bs[nxt][(ar + 64) * APAD + ac], Bsrc + (size_t)(ar + 64) * CC + c0 + ac);
            cp_commit();
            cp_wait1();
        } else {
            cp_wait0();
        }
        __syncthreads();

#pragma unroll
        for (int kk = 0; kk < 2; kk++) {
            unsigned a[4][4], bb[4][2];
#pragma unroll
            for (int mm = 0; mm < 4; mm++) {
                const __half* p = &As[cur][(wm * 64 + mm * 16 + g) * APAD + kk * 16 + 2 * tt];
                a[mm][0] = *(const unsigned*)p;
                a[mm][1] = *(const unsigned*)(p + 8 * APAD);
                a[mm][2] = *(const unsigned*)(p + 8);
                a[mm][3] = *(const unsigned*)(p + 8 * APAD + 8);
            }
#pragma unroll
            for (int nn = 0; nn < 4; nn++) {
                const __half* p = &Bs[cur][(wn * 32 + nn * 8 + g) * APAD + kk * 16 + 2 * tt];
                bb[nn][0] = *(const unsigned*)p;
                bb[nn][1] = *(const unsigned*)(p + 8);
            }
#pragma unroll
            for (int mm = 0; mm < 4; mm++)
#pragma unroll
                for (int nn = 0; nn < 4; nn++) mma_f16(acc[mm][nn], a[mm], bb[nn]);
        }
        __syncthreads();
    }

    if (isqk) {
#pragma unroll
        for (int mm = 0; mm < 4; mm++) {
            int l = l0 + wm * 64 + mm * 16 + g;
#pragma unroll
            for (int nn = 0; nn < 4; nn++) {
                int o = o0 + wn * 32 + nn * 8 + 2 * tt;
                int sec = o >> 9, head = (o >> 6) & 7, ch = o & 63;
                float sc = (sec == 0) ? 0.125f : 1.f;  // fold attn scale into q
                __half* dst = g_qkT + (((size_t)b * 2 + sec) * 8 + head) * LL * CHH;
                float2 b2 = *(const float2*)&bias[o];
                *(__half2*)&dst[(size_t)l * CHH + ch] =
                    __floats2half2_rn((acc[mm][nn][0] + b2.x) * sc, (acc[mm][nn][1] + b2.y) * sc);
                *(__half2*)&dst[(size_t)(l + 8) * CHH + ch] =
                    __floats2half2_rn((acc[mm][nn][2] + b2.x) * sc, (acc[mm][nn][3] + b2.y) * sc);
            }
        }
    } else {
        __half* dst = g_v + (size_t)b * CC * LL;
#pragma unroll
        for (int mm = 0; mm < 4; mm++) {
            int o = o0 + wm * 64 + mm * 16 + g;
            float b0 = bias[2 * CC + o], b1 = bias[2 * CC + o + 8];
#pragma unroll
            for (int nn = 0; nn < 4; nn++) {
                int l = l0 + wn * 32 + nn * 8 + 2 * tt;
                *(__half2*)&dst[(size_t)o * LL + l] =
                    __floats2half2_rn(acc[mm][nn][0] + b0, acc[mm][nn][1] + b0);
                *(__half2*)&dst[(size_t)(o + 8) * LL + l] =
                    __floats2half2_rn(acc[mm][nn][2] + b1, acc[mm][nn][3] + b1);
            }
        }
    }
}

// ---------------------------------------------------------------------------
// Kernel 3: flash attention (fp16 HMMA, online softmax, 4 warps, 64-q tile).
// Q pre-scaled by 1/8. Q,K in [l][ch]; V in [ch][l]. P stays in registers.
// ---------------------------------------------------------------------------
#define FPAD 72
#define Q_BYTES (64 * FPAD * 2)
#define KVB_BYTES (64 * FPAD * 2)
#define FSMEM (Q_BYTES + 4 * KVB_BYTES)
#define AS_ST 68

__global__ void __launch_bounds__(128, 4) attn_flash(const float* __restrict__ x,
                                                     float* __restrict__ out) {
    extern __shared__ char smc[];
    __half* Qs = (__half*)smc;
    __half* Kb[2] = {(__half*)(smc + Q_BYTES), (__half*)(smc + Q_BYTES + 2 * KVB_BYTES)};
    __half* Vb[2] = {(__half*)(smc + Q_BYTES + KVB_BYTES), (__half*)(smc + Q_BYTES + 3 * KVB_BYTES)};

    int q0 = blockIdx.x;                 // 0..15 (64 queries each)
    int bh = blockIdx.y;                 // 0..127
    int b = bh >> 3, head = bh & 7;
    int t = threadIdx.x, warp = t >> 5, lane = t & 31;
    int g = lane >> 2, tt = lane & 3;

    const __half* qbase = g_qkT + (((size_t)b * 2 + 0) * 8 + head) * LL * CHH;
    const __half* kbase = g_qkT + (((size_t)b * 2 + 1) * 8 + head) * LL * CHH;
    const __half* vbase = g_v + ((size_t)b * CC + head * CHH) * LL;

    // staging: 512 16B-chunks per 64x64 fp16 tile, 4 per thread
    // row_i = sr + 16*i (col invariant across i)
    int sr = t >> 3, sc = (t & 7) * 8;

    // prologue: Q + chunk0 (group0), chunk1 (group1)
#pragma unroll
    for (int i = 0; i < 4; i++) {
        int rw = sr + i * 16;
        cp16h(&Qs[rw * FPAD + sc], qbase + (size_t)(q0 * 64 + rw) * CHH + sc);
        cp16h(&Kb[0][rw * FPAD + sc], kbase + (size_t)rw * CHH + sc);
        cp16h(&Vb[0][rw * FPAD + sc], vbase + (size_t)rw * LL + sc);
    }
    cp_commit();
#pragma unroll
    for (int i = 0; i < 4; i++) {
        int rw = sr + i * 16;
        cp16h(&Kb[1][rw * FPAD + sc], kbase + (size_t)(64 + rw) * CHH + sc);
        cp16h(&Vb[1][rw * FPAD + sc], vbase + (size_t)rw * LL + 64 + sc);
    }
    cp_commit();

    float m0 = -INFINITY, m1 = -INFINITY, l0 = 0.f, l1 = 0.f;
    float o[8][4];
#pragma unroll
    for (int j = 0; j < 8; j++)
#pragma unroll
        for (int r = 0; r < 4; r++) o[j][r] = 0.f;

    unsigned qa[4][4];
    bool qloaded = false;

    for (int ic = 0; ic < 16; ic++) {
        if (ic < 15) cp_wait1(); else cp_wait0();
        __syncthreads();

        if (!qloaded) {
            const __half* qp = &Qs[(warp * 16 + g) * FPAD];
#pragma unroll
            for (int kk = 0; kk < 4; kk++) {
                const __half* p = qp + kk * 16 + 2 * tt;
                qa[kk][0] = *(const unsigned*)p;
                qa[kk][1] = *(const unsigned*)(p + 8 * FPAD);
                qa[kk][2] = *(const unsigned*)(p + 8);
                qa[kk][3] = *(const unsigned*)(p + 8 * FPAD + 8);
            }
            qloaded = true;
        }

        __half* K = Kb[ic & 1];
        __half* V = Vb[ic & 1];

        // ---- S = Q K^T (16q x 64s per warp); scale already in Q ----
        float d[8][4];
#pragma unroll
        for (int j = 0; j < 8; j++) {
            d[j][0] = d[j][1] = d[j][2] = d[j][3] = 0.f;
            const __half* kp = &K[(j * 8 + g) * FPAD + 2 * tt];
#pragma unroll
            for (int kk = 0; kk < 4; kk++) {
                unsigned bf[2];
                bf[0] = *(const unsigned*)(kp + kk * 16);
                bf[1] = *(const unsigned*)(kp + kk * 16 + 8);
                mma_f16(d[j], qa[kk], bf);
            }
        }

        // ---- online softmax update ----
        float cm0 = -INFINITY, cm1 = -INFINITY;
#pragma unroll
        for (int j = 0; j < 8; j++) {
            cm0 = fmaxf(cm0, fmaxf(d[j][0], d[j][1]));
            cm1 = fmaxf(cm1, fmaxf(d[j][2], d[j][3]));
        }
        cm0 = fmaxf(cm0, __shfl_xor_sync(0xffffffffu, cm0, 1));
        cm0 = fmaxf(cm0, __shfl_xor_sync(0xffffffffu, cm0, 2));
        cm1 = fmaxf(cm1, __shfl_xor_sync(0xffffffffu, cm1, 1));
        cm1 = fmaxf(cm1, __shfl_xor_sync(0xffffffffu, cm1, 2));

        float mn0 = fmaxf(m0, cm0), mn1 = fmaxf(m1, cm1);
        float al0 = __expf(m0 - mn0), al1 = __expf(m1 - mn1);
        m0 = mn0; m1 = mn1;

        float rs0 = 0.f, rs1 = 0.f;
        unsigned p2[8][2];
#pragma unroll
        for (int j = 0; j < 8; j++) {
            float e0 = __expf(d[j][0] - m0);
            float e1 = __expf(d[j][1] - m0);
            float e2 = __expf(d[j][2] - m1);
            float e3 = __expf(d[j][3] - m1);
            rs0 += e0 + e1; rs1 += e2 + e3;
            __half2 h01 = __floats2half2_rn(e0, e1);
            __half2 h23 = __floats2half2_rn(e2, e3);
            p2[j][0] = *(unsigned*)&h01;
            p2[j][1] = *(unsigned*)&h23;
        }
        rs0 += __shfl_xor_sync(0xffffffffu, rs0, 1);
        rs0 += __shfl_xor_sync(0xffffffffu, rs0, 2);
        rs1 += __shfl_xor_sync(0xffffffffu, rs1, 1);
        rs1 += __shfl_xor_sync(0xffffffffu, rs1, 2);
        l0 = l0 * al0 + rs0;
        l1 = l1 * al1 + rs1;

#pragma unroll
        for (int j = 0; j < 8; j++) {
            o[j][0] *= al0; o[j][1] *= al0;
            o[j][2] *= al1; o[j][3] *= al1;
        }

        // ---- O += P V^T ----
#pragma unroll
        for (int j = 0; j < 8; j++) {
            const __half* vp = &V[(j * 8 + g) * FPAD + 2 * tt];
#pragma unroll
            for (int kk = 0; kk < 4; kk++) {
                unsigned a[4] = {p2[2 * kk][0], p2[2 * kk][1],
                                 p2[2 * kk + 1][0], p2[2 * kk + 1][1]};
                unsigned bf[2];
                bf[0] = *(const unsigned*)(vp + kk * 16);
                bf[1] = *(const unsigned*)(vp + kk * 16 + 8);
                mma_f16(o[j], a, bf);
            }
        }

        __syncthreads();
        if (ic + 2 < 16) {
            __half* Kn = Kb[ic & 1];
            __half* Vn = Vb[ic & 1];
            int s0 = (ic + 2) * 64;
#pragma unroll
            for (int i = 0; i < 4; i++) {
                int rw = sr + i * 16;
                cp16h(&Kn[rw * FPAD + sc], kbase + (size_t)(s0 + rw) * CHH + sc);
                cp16h(&Vn[rw * FPAD + sc], vbase + (size_t)rw * LL + s0 + sc);
            }
            cp_commit();
        }
    }

    // ---- epilogue: A[ch][q] staged in smem, coalesced residual-add ----
    float* AS = (float*)smc;
    float inv0 = 1.f / l0, inv1 = 1.f / l1;
    int qg = warp * 16 + g;
#pragma unroll
    for (int j = 0; j < 8; j++) {
        int ch = j * 8 + 2 * tt;
        AS[ch * AS_ST + qg] = o[j][0] * inv0;
        AS[(ch + 1) * AS_ST + qg] = o[j][1] * inv0;
        AS[ch * AS_ST + qg + 8] = o[j][2] * inv1;
        AS[(ch + 1) * AS_ST + qg + 8] = o[j][3] * inv1;
    }
    __syncthreads();
#pragma unroll
    for (int k = 0; k < 32; k++) {
        int idx = t + k * 128;
        int ch = idx >> 6, q = idx & 63;
        size_t gi = ((size_t)b * CC + head * CHH + ch) * LL + q0 * 64 + q;
        out[gi] = x[gi] + AS[ch * AS_ST + q];
    }
}

// ---------------------------------------------------------------------------
extern "C" void kernel_launch(void* const* d_in, const int* in_sizes, int n_in,
                              void* d_out, int out_size) {
    const float* x = (const float*)d_in[0];
    const float* gn_w = (const float*)d_in[1];
    const float* gn_b = (const float*)d_in[2];
    const float* conv_w = (const float*)d_in[3];
    const float* conv_b = (const float*)d_in[4];
    float* out = (float*)d_out;

    wconv_kernel<<<3 * CC * CC / 512, 256>>>(conv_w);
    gn_kernel<<<BB * GG, 256>>>(x, gn_w, gn_b);
    qkv_gemm<<<1536, 256>>>(conv_b);

    cudaFuncSetAttribute(attn_flash, cudaFuncAttributeMaxDynamicSharedMemorySize,
                         FSMEM);
    dim3 attn_grid(LL / 64, BB * HEADS);
    attn_flash<<<attn_grid, 128, FSMEM>>>(x, out);
}

// round 8
// speedup vs baseline: 16.0393x; 1.2110x over previous
#include <cuda_runtime.h>
#include <cuda_fp16.h>
#include <cstdint>
#include <math.h>

#define BB 16
#define CC 512
#define LL 1024
#define GG 32
#define CPG 16
#define HEADS 8
#define CHH 64

// Scratch (no allocation allowed)
__device__ __half g_hT[BB * LL * CC];                 // h transposed [b][l][c], fp16
__device__ __half g_wh[3 * CC * CC];                  // conv weight fp16
__device__ __half g_qkT[BB * 2 * HEADS * LL * CHH];   // q,k transposed; q pre-scaled by 1/8
__device__ __half g_v[BB * CC * LL];                  // v natural [b][ch_global][l]

__device__ __forceinline__ void mma_f16(float d[4], const unsigned a[4], const unsigned b[2]) {
    asm volatile(
        "mma.sync.aligned.m16n8k16.row.col.f32.f16.f16.f32 "
        "{%0,%1,%2,%3}, {%4,%5,%6,%7}, {%8,%9}, {%0,%1,%2,%3};"
        : "+f"(d[0]), "+f"(d[1]), "+f"(d[2]), "+f"(d[3])
        : "r"(a[0]), "r"(a[1]), "r"(a[2]), "r"(a[3]),
          "r"(b[0]), "r"(b[1]));
}

__device__ __forceinline__ void ldsm4(unsigned r[4], unsigned saddr) {
    asm volatile("ldmatrix.sync.aligned.m8n8.x4.shared.b16 {%0,%1,%2,%3}, [%4];"
                 : "=r"(r[0]), "=r"(r[1]), "=r"(r[2]), "=r"(r[3]) : "r"(saddr));
}

__device__ __forceinline__ void cp16h(__half* dst_smem, const __half* src) {
    unsigned d = (unsigned)__cvta_generic_to_shared(dst_smem);
    asm volatile("cp.async.cg.shared.global [%0], [%1], 16;" :: "r"(d), "l"(src));
}
__device__ __forceinline__ void cp_commit() { asm volatile("cp.async.commit_group;"); }
__device__ __forceinline__ void cp_wait1() { asm volatile("cp.async.wait_group 1;"); }
__device__ __forceinline__ void cp_wait0() { asm volatile("cp.async.wait_group 0;"); }

// ---------------------------------------------------------------------------
// Kernel 0: convert conv weight to fp16.
// ---------------------------------------------------------------------------
__global__ void wconv_kernel(const float* __restrict__ W) {
    int i = blockIdx.x * 256 + threadIdx.x;
    float2 w = ((const float2*)W)[i];
    ((__half2*)g_wh)[i] = __floats2half2_rn(w.x, w.y);
}

// ---------------------------------------------------------------------------
// Kernel 1: GroupNorm(32) -> hT [b][l][c] fp16. One block per (b, g).
// ---------------------------------------------------------------------------
__global__ void gn_kernel(const float* __restrict__ x,
                          const float* __restrict__ gw,
                          const float* __restrict__ gb) {
    int bg = blockIdx.x;
    int b = bg >> 5, g = bg & 31;
    const float* xp = x + ((size_t)b * CC + (size_t)g * CPG) * LL;
    const float4* xp4 = (const float4*)xp;
    int t = threadIdx.x;

    float s = 0.f, ss = 0.f;
    for (int i = t; i < CPG * LL / 4; i += 256) {
        float4 v = xp4[i];
        s += v.x + v.y + v.z + v.w;
        ss += v.x * v.x + v.y * v.y + v.z * v.z + v.w * v.w;
    }
    __shared__ float r0[256], r1[256];
    r0[t] = s; r1[t] = ss;
    __syncthreads();
    for (int o = 128; o > 0; o >>= 1) {
        if (t < o) { r0[t] += r0[t + o]; r1[t] += r1[t + o]; }
        __syncthreads();
    }
    const float invN = 1.f / (CPG * LL);
    float mean = r0[0] * invN;
    float var = r1[0] * invN - mean * mean;
    float rstd = rsqrtf(var + 1e-5f);

    int h = t & 1;
    float wv[8], bv[8];
#pragma unroll
    for (int j = 0; j < 8; j++) {
        int cg = g * CPG + h * 8 + j;
        wv[j] = gw[cg] * rstd;
        bv[j] = gb[cg] - mean * wv[j];
    }

    for (int u = t; u < 2 * LL; u += 256) {
        int l = u >> 1;
        uint4 pack;
        __half2* ph = (__half2*)&pack;
#pragma unroll
        for (int j = 0; j < 4; j++) {
            float v0 = xp[(size_t)(h * 8 + 2 * j) * LL + l];
            float v1 = xp[(size_t)(h * 8 + 2 * j + 1) * LL + l];
            ph[j] = __floats2half2_rn(v0 * wv[2 * j] + bv[2 * j],
                                      v1 * wv[2 * j + 1] + bv[2 * j + 1]);
        }
        *(uint4*)(g_hT + ((size_t)b * LL + l) * CC + g * CPG + h * 8) = pack;
    }
}

// ---------------------------------------------------------------------------
// Kernel 2: unified QKV GEMM, 128x128 block tiles, ldmatrix fragment loads.
// ---------------------------------------------------------------------------
#define APAD 40

__global__ void __launch_bounds__(256, 2) qkv_gemm(const float* __restrict__ bias) {
    __shared__ __half As[2][128 * APAD];
    __shared__ __half Bs[2][128 * APAD];

    int id = blockIdx.x;
    bool isqk = id < 1024;
    int b, o0, l0;
    const __half *Asrc, *Bsrc;
    if (isqk) {
        int r = id & 63;
        b = id >> 6;
        l0 = (r & 7) * 128; o0 = (r >> 3) * 128;
        Asrc = g_hT + ((size_t)b * LL + l0) * CC;
        Bsrc = g_wh + (size_t)o0 * CC;
    } else {
        int id2 = id - 1024;
        int r = id2 & 31;
        b = id2 >> 5;
        l0 = (r & 7) * 128; o0 = (r >> 3) * 128;
        Asrc = g_wh + (size_t)(2 * CC + o0) * CC;
        Bsrc = g_hT + ((size_t)b * LL + l0) * CC;
    }
    int t = threadIdx.x, warp = t >> 5, lane = t & 31;
    int g = lane >> 2, tt = lane & 3;
    int wm = warp >> 2, wn = warp & 3;   // 2 x 4 warps, warp tile 64x32

    int ar = t >> 2, ac = (t & 3) * 8;

    // ldmatrix lane offsets (in half units)
    int arow = (lane & 7) + 8 * ((lane >> 3) & 1);  // A: rows split by bit3
    int acol = 8 * (lane >> 4);                      // A: k-half by bit4
    int brow = (lane & 7) + 8 * ((lane >> 4) & 1);   // B: rows split by bit4
    int bcol = 8 * ((lane >> 3) & 1);                // B: k-half by bit3
    unsigned aoff = (unsigned)((wm * 64 + arow) * APAD + acol) * 2;
    unsigned boff = (unsigned)((wn * 32 + brow) * APAD + bcol) * 2;
    unsigned sA[2] = {(unsigned)__cvta_generic_to_shared(&As[0][0]) + aoff,
                      (unsigned)__cvta_generic_to_shared(&As[1][0]) + aoff};
    unsigned sB[2] = {(unsigned)__cvta_generic_to_shared(&Bs[0][0]) + boff,
                      (unsigned)__cvta_generic_to_shared(&Bs[1][0]) + boff};

    float acc[4][4][4];
#pragma unroll
    for (int m = 0; m < 4; m++)
#pragma unroll
        for (int n = 0; n < 4; n++)
#pragma unroll
            for (int r = 0; r < 4; r++) acc[m][n][r] = 0.f;

    cp16h(&As[0][ar * APAD + ac], Asrc + (size_t)ar * CC + ac);
    cp16h(&As[0][(ar + 64) * APAD + ac], Asrc + (size_t)(ar + 64) * CC + ac);
    cp16h(&Bs[0][ar * APAD + ac], Bsrc + (size_t)ar * CC + ac);
    cp16h(&Bs[0][(ar + 64) * APAD + ac], Bsrc + (size_t)(ar + 64) * CC + ac);
    cp_commit();

    for (int ic = 0; ic < 16; ic++) {
        int cur = ic & 1;
        if (ic + 1 < 16) {
            int nxt = cur ^ 1, c0 = (ic + 1) * 32;
            cp16h(&As[nxt][ar * APAD + ac], Asrc + (size_t)ar * CC + c0 + ac);
            cp16h(&As[nxt][(ar + 64) * APAD + ac], Asrc + (size_t)(ar + 64) * CC + c0 + ac);
            cp16h(&Bs[nxt][ar * APAD + ac], Bsrc + (size_t)ar * CC + c0 + ac);
            cp16h(&Bs[nxt][(ar + 64) * APAD + ac], Bsrc + (size_t)(ar + 64) * CC + c0 + ac);
            cp_commit();
            cp_wait1();
        } else {
            cp_wait0();
        }
        __syncthreads();

#pragma unroll
        for (int kk = 0; kk < 2; kk++) {
            unsigned a[4][4], bb[4][4];
#pragma unroll
            for (int mm = 0; mm < 4; mm++)
                ldsm4(a[mm], sA[cur] + (unsigned)(mm * 16 * APAD + kk * 16) * 2);
#pragma unroll
            for (int i = 0; i < 2; i++)   // bb[2i], bb[2i+1] packed in one x4
                ldsm4(bb[2 * i], sB[cur] + (unsigned)(i * 16 * APAD + kk * 16) * 2);
#pragma unroll
            for (int mm = 0; mm < 4; mm++)
#pragma unroll
                for (int nn = 0; nn < 4; nn++) {
                    unsigned bf[2] = {bb[2 * (nn >> 1)][2 * (nn & 1)],
                                      bb[2 * (nn >> 1)][2 * (nn & 1) + 1]};
                    mma_f16(acc[mm][nn], a[mm], bf);
                }
        }
        __syncthreads();
    }

    if (isqk) {
#pragma unroll
        for (int mm = 0; mm < 4; mm++) {
            int l = l0 + wm * 64 + mm * 16 + g;
#pragma unroll
            for (int nn = 0; nn < 4; nn++) {
                int o = o0 + wn * 32 + nn * 8 + 2 * tt;
                int sec = o >> 9, head = (o >> 6) & 7, ch = o & 63;
                float sc = (sec == 0) ? 0.125f : 1.f;
                __half* dst = g_qkT + (((size_t)b * 2 + sec) * 8 + head) * LL * CHH;
                float2 b2 = *(const float2*)&bias[o];
                *(__half2*)&dst[(size_t)l * CHH + ch] =
                    __floats2half2_rn((acc[mm][nn][0] + b2.x) * sc, (acc[mm][nn][1] + b2.y) * sc);
                *(__half2*)&dst[(size_t)(l + 8) * CHH + ch] =
                    __floats2half2_rn((acc[mm][nn][2] + b2.x) * sc, (acc[mm][nn][3] + b2.y) * sc);
            }
        }
    } else {
        __half* dst = g_v + (size_t)b * CC * LL;
#pragma unroll
        for (int mm = 0; mm < 4; mm++) {
            int o = o0 + wm * 64 + mm * 16 + g;
            float b0 = bias[2 * CC + o], b1 = bias[2 * CC + o + 8];
#pragma unroll
            for (int nn = 0; nn < 4; nn++) {
                int l = l0 + wn * 32 + nn * 8 + 2 * tt;
                *(__half2*)&dst[(size_t)o * LL + l] =
                    __floats2half2_rn(acc[mm][nn][0] + b0, acc[mm][nn][1] + b0);
                *(__half2*)&dst[(size_t)(o + 8) * LL + l] =
                    __floats2half2_rn(acc[mm][nn][2] + b1, acc[mm][nn][3] + b1);
            }
        }
    }
}

// ---------------------------------------------------------------------------
// Kernel 3: flash attention (fp16 HMMA + ldmatrix, online softmax, 4 warps).
// ---------------------------------------------------------------------------
#define FPAD 72
#define Q_BYTES (64 * FPAD * 2)
#define KVB_BYTES (64 * FPAD * 2)
#define FSMEM (Q_BYTES + 4 * KVB_BYTES)
#define AS_ST 68

__global__ void __launch_bounds__(128, 4) attn_flash(const float* __restrict__ x,
                                                     float* __restrict__ out) {
    extern __shared__ char smc[];
    __half* Qs = (__half*)smc;
    __half* Kb[2] = {(__half*)(smc + Q_BYTES), (__half*)(smc + Q_BYTES + 2 * KVB_BYTES)};
    __half* Vb[2] = {(__half*)(smc + Q_BYTES + KVB_BYTES), (__half*)(smc + Q_BYTES + 3 * KVB_BYTES)};

    int q0 = blockIdx.x;                 // 0..15 (64 queries each)
    int bh = blockIdx.y;                 // 0..127
    int b = bh >> 3, head = bh & 7;
    int t = threadIdx.x, warp = t >> 5, lane = t & 31;
    int g = lane >> 2, tt = lane & 3;

    const __half* qbase = g_qkT + (((size_t)b * 2 + 0) * 8 + head) * LL * CHH;
    const __half* kbase = g_qkT + (((size_t)b * 2 + 1) * 8 + head) * LL * CHH;
    const __half* vbase = g_v + ((size_t)b * CC + head * CHH) * LL;

    int sr = t >> 3, sc = (t & 7) * 8;

    // ldmatrix B-pattern lane offset (row by bit4, k-half by bit3)
    int brow = (lane & 7) + 8 * ((lane >> 4) & 1);
    int bcol = 8 * ((lane >> 3) & 1);
    unsigned kvoff = (unsigned)(brow * FPAD + bcol) * 2;
    unsigned sK[2] = {(unsigned)__cvta_generic_to_shared(Kb[0]) + kvoff,
                      (unsigned)__cvta_generic_to_shared(Kb[1]) + kvoff};
    unsigned sV[2] = {(unsigned)__cvta_generic_to_shared(Vb[0]) + kvoff,
                      (unsigned)__cvta_generic_to_shared(Vb[1]) + kvoff};

    // prologue: Q + chunk0 (group0), chunk1 (group1)
#pragma unroll
    for (int i = 0; i < 4; i++) {
        int rw = sr + i * 16;
        cp16h(&Qs[rw * FPAD + sc], qbase + (size_t)(q0 * 64 + rw) * CHH + sc);
        cp16h(&Kb[0][rw * FPAD + sc], kbase + (size_t)rw * CHH + sc);
        cp16h(&Vb[0][rw * FPAD + sc], vbase + (size_t)rw * LL + sc);
    }
    cp_commit();
#pragma unroll
    for (int i = 0; i < 4; i++) {
        int rw = sr + i * 16;
        cp16h(&Kb[1][rw * FPAD + sc], kbase + (size_t)(64 + rw) * CHH + sc);
        cp16h(&Vb[1][rw * FPAD + sc], vbase + (size_t)rw * LL + 64 + sc);
    }
    cp_commit();

    float m0 = -INFINITY, m1 = -INFINITY, l0 = 0.f, l1 = 0.f;
    float o[8][4];
#pragma unroll
    for (int j = 0; j < 8; j++)
#pragma unroll
        for (int r = 0; r < 4; r++) o[j][r] = 0.f;

    unsigned qa[4][4];
    bool qloaded = false;

    for (int ic = 0; ic < 16; ic++) {
        if (ic < 15) cp_wait1(); else cp_wait0();
        __syncthreads();

        if (!qloaded) {
            const __half* qp = &Qs[(warp * 16 + g) * FPAD];
#pragma unroll
            for (int kk = 0; kk < 4; kk++) {
                const __half* p = qp + kk * 16 + 2 * tt;
                qa[kk][0] = *(const unsigned*)p;
                qa[kk][1] = *(const unsigned*)(p + 8 * FPAD);
                qa[kk][2] = *(const unsigned*)(p + 8);
                qa[kk][3] = *(const unsigned*)(p + 8 * FPAD + 8);
            }
            qloaded = true;
        }

        unsigned K = sK[ic & 1], V = sV[ic & 1];

        // ---- S = Q K^T (16q x 64s per warp); scale already in Q ----
        float d[8][4];
#pragma unroll
        for (int j = 0; j < 8; j++)
            d[j][0] = d[j][1] = d[j][2] = d[j][3] = 0.f;
#pragma unroll
        for (int kk = 0; kk < 4; kk++) {
#pragma unroll
            for (int i = 0; i < 4; i++) {   // j pair (2i, 2i+1)
                unsigned r[4];
                ldsm4(r, K + (unsigned)(i * 16 * FPAD + kk * 16) * 2);
                unsigned blo[2] = {r[0], r[1]}, bhi[2] = {r[2], r[3]};
                mma_f16(d[2 * i], qa[kk], blo);
                mma_f16(d[2 * i + 1], qa[kk], bhi);
            }
        }

        // ---- online softmax update ----
        float cm0 = -INFINITY, cm1 = -INFINITY;
#pragma unroll
        for (int j = 0; j < 8; j++) {
            cm0 = fmaxf(cm0, fmaxf(d[j][0], d[j][1]));
            cm1 = fmaxf(cm1, fmaxf(d[j][2], d[j][3]));
        }
        cm0 = fmaxf(cm0, __shfl_xor_sync(0xffffffffu, cm0, 1));
        cm0 = fmaxf(cm0, __shfl_xor_sync(0xffffffffu, cm0, 2));
        cm1 = fmaxf(cm1, __shfl_xor_sync(0xffffffffu, cm1, 1));
        cm1 = fmaxf(cm1, __shfl_xor_sync(0xffffffffu, cm1, 2));

        float mn0 = fmaxf(m0, cm0), mn1 = fmaxf(m1, cm1);
        float al0 = __expf(m0 - mn0), al1 = __expf(m1 - mn1);
        m0 = mn0; m1 = mn1;

        float rs0 = 0.f, rs1 = 0.f;
        unsigned p2[8][2];
#pragma unroll
        for (int j = 0; j < 8; j++) {
            float e0 = __expf(d[j][0] - m0);
            float e1 = __expf(d[j][1] - m0);
            float e2 = __expf(d[j][2] - m1);
            float e3 = __expf(d[j][3] - m1);
            rs0 += e0 + e1; rs1 += e2 + e3;
            __half2 h01 = __floats2half2_rn(e0, e1);
            __half2 h23 = __floats2half2_rn(e2, e3);
            p2[j][0] = *(unsigned*)&h01;
            p2[j][1] = *(unsigned*)&h23;
        }
        rs0 += __shfl_xor_sync(0xffffffffu, rs0, 1);
        rs0 += __shfl_xor_sync(0xffffffffu, rs0, 2);
        rs1 += __shfl_xor_sync(0xffffffffu, rs1, 1);
        rs1 += __shfl_xor_sync(0xffffffffu, rs1, 2);
        l0 = l0 * al0 + rs0;
        l1 = l1 * al1 + rs1;

#pragma unroll
        for (int j = 0; j < 8; j++) {
            o[j][0] *= al0; o[j][1] *= al0;
            o[j][2] *= al1; o[j][3] *= al1;
        }

        // ---- O += P V^T ----
#pragma unroll
        for (int kk = 0; kk < 4; kk++) {
            unsigned a[4] = {p2[2 * kk][0], p2[2 * kk][1],
                             p2[2 * kk + 1][0], p2[2 * kk + 1][1]};
#pragma unroll
            for (int i = 0; i < 4; i++) {   // ch pair (2i, 2i+1)
                unsigned r[4];
                ldsm4(r, V + (unsigned)(i * 16 * FPAD + kk * 16) * 2);
                unsigned blo[2] = {r[0], r[1]}, bhi[2] = {r[2], r[3]};
                mma_f16(o[2 * i], a, blo);
                mma_f16(o[2 * i + 1], a, bhi);
            }
        }

        __syncthreads();
        if (ic + 2 < 16) {
            __half* Kn = Kb[ic & 1];
            __half* Vn = Vb[ic & 1];
            int s0 = (ic + 2) * 64;
#pragma unroll
            for (int i = 0; i < 4; i++) {
                int rw = sr + i * 16;
                cp16h(&Kn[rw * FPAD + sc], kbase + (size_t)(s0 + rw) * CHH + sc);
                cp16h(&Vn[rw * FPAD + sc], vbase + (size_t)rw * LL + s0 + sc);
            }
            cp_commit();
        }
    }

    // ---- epilogue: A[ch][q] staged in smem, coalesced residual-add ----
    float* AS = (float*)smc;
    float inv0 = 1.f / l0, inv1 = 1.f / l1;
    int qg = warp * 16 + g;
#pragma unroll
    for (int j = 0; j < 8; j++) {
        int ch = j * 8 + 2 * tt;
        AS[ch * AS_ST + qg] = o[j][0] * inv0;
        AS[(ch + 1) * AS_ST + qg] = o[j][1] * inv0;
        AS[ch * AS_ST + qg + 8] = o[j][2] * inv1;
        AS[(ch + 1) * AS_ST + qg + 8] = o[j][3] * inv1;
    }
    __syncthreads();
#pragma unroll
    for (int k = 0; k < 32; k++) {
        int idx = t + k * 128;
        int ch = idx >> 6, q = idx & 63;
        size_t gi = ((size_t)b * CC + head * CHH + ch) * LL + q0 * 64 + q;
        out[gi] = x[gi] + AS[ch * AS_ST + q];
    }
}

// ---------------------------------------------------------------------------
extern "C" void kernel_launch(void* const* d_in, const int* in_sizes, int n_in,
                              void* d_out, int out_size) {
    const float* x = (const float*)d_in[0];
    const float* gn_w = (const float*)d_in[1];
    const float* gn_b = (const float*)d_in[2];
    const float* conv_w = (const float*)d_in[3];
    const float* conv_b = (const float*)d_in[4];
    float* out = (float*)d_out;

    wconv_kernel<<<3 * CC * CC / 512, 256>>>(conv_w);
    gn_kernel<<<BB * GG, 256>>>(x, gn_w, gn_b);
    qkv_gemm<<<1536, 256>>>(conv_b);

    cudaFuncSetAttribute(attn_flash, cudaFuncAttributeMaxDynamicSharedMemorySize,
                         FSMEM);
    dim3 attn_grid(LL / 64, BB * HEADS);
    attn_flash<<<attn_grid, 128, FSMEM>>>(x, out);
}